// round 9
// baseline (speedup 1.0000x reference)
#include <cuda_runtime.h>
#include <cuda_bf16.h>
#include <cstdint>
#include <math.h>

#define B   2
#define NS  512
#define H   768
#define C   108
#define D   64
#define PIX (NS*NS)
#define CH_HID 6
#define MROWS (C*NS)
#define NSPLIT 4
#define CSPL  (C/NSPLIT)     // 27

// ---------------- device scratch ----------------
__device__ float          g_qw[B*NS*D];
__device__ float          g_kw[B*NS*D];
__device__ float          g_ev[C*D];
__device__ float          g_Qs[B*D];
__device__ float          g_Ks[B*D];
__device__ float          g_evS[B*D];
__device__ unsigned       g_chanMaxKey[B*C];
__device__ float          g_scale[B*C];
__device__ float          g_cmax[NSPLIT][B*PIX];   // 8 MB: per-split pixel max
__device__ float          g_compMean[B*PIX];
__device__ float          g_sig[B*PIX];
__device__ __nv_bfloat16  g_A[B*MROWS*D];          // 14.2 MB: bf16(ev*q)
__device__ __nv_bfloat16  g_Kb[B*NS*D];            // bf16(k)

__device__ __forceinline__ unsigned fkey(float f){
    unsigned u = __float_as_uint(f);
    return (u & 0x80000000u) ? ~u : (u | 0x80000000u);
}
__device__ __forceinline__ float fkeyinv(unsigned k){
    return __uint_as_float((k & 0x80000000u) ? (k & 0x7fffffffu) : ~k);
}
__device__ __forceinline__ uint32_t smem_u32(const void* p){
    uint32_t a;
    asm("{ .reg .u64 t; cvta.to.shared.u64 t, %1; cvt.u32.u64 %0, t; }" : "=r"(a) : "l"(p));
    return a;
}
__device__ __forceinline__ uint32_t swz128(uint32_t off){ return off ^ ((off >> 3) & 0x70); }

// ---- warp-level bf16 tensor core ops (baseline PTX; works on .target sm_100) ----
__device__ __forceinline__ void ldm_x4(uint32_t* r, uint32_t addr){
    asm volatile("ldmatrix.sync.aligned.m8n8.x4.shared.b16 {%0,%1,%2,%3}, [%4];"
        : "=r"(r[0]), "=r"(r[1]), "=r"(r[2]), "=r"(r[3]) : "r"(addr));
}
__device__ __forceinline__ void ldm_x2(uint32_t* r, uint32_t addr){
    asm volatile("ldmatrix.sync.aligned.m8n8.x2.shared.b16 {%0,%1}, [%2];"
        : "=r"(r[0]), "=r"(r[1]) : "r"(addr));
}
__device__ __forceinline__ void mma16816(float* c, const uint32_t* a, const uint32_t* b){
    asm volatile("mma.sync.aligned.m16n8k16.row.col.f32.bf16.bf16.f32 "
        "{%0,%1,%2,%3}, {%4,%5,%6,%7}, {%8,%9}, {%0,%1,%2,%3};"
        : "+f"(c[0]), "+f"(c[1]), "+f"(c[2]), "+f"(c[3])
        : "r"(a[0]), "r"(a[1]), "r"(a[2]), "r"(a[3]), "r"(b[0]), "r"(b[1]));
}

// ---------------- K0 ----------------
__global__ void k0_init(){
    int i = threadIdx.x;
    if (i < B*C) g_chanMaxKey[i] = 0u;
}

// ---------------- K1: dense + RoPE ----------------
#define K1_M 8
__global__ __launch_bounds__(128) void k1_qk(const float* __restrict__ inp,
                                             const float* __restrict__ wd,
                                             const float* __restrict__ bd){
    __shared__ float in_s[K1_M][H];
    __shared__ float seq_s[K1_M][128];
    const int b = blockIdx.y, m0 = blockIdx.x * K1_M, tid = threadIdx.x;

    const float* src = inp + ((size_t)b*NS + m0) * H;
    for (int i = tid; i < K1_M*H; i += 128) in_s[i/H][i%H] = src[i];
    __syncthreads();

    const int col = tid;
    float acc[K1_M];
#pragma unroll
    for (int mi = 0; mi < K1_M; mi++) acc[mi] = 0.f;
#pragma unroll 1
    for (int h = 0; h < H; h += 4){
        float w0 = wd[(h+0)*128 + col];
        float w1 = wd[(h+1)*128 + col];
        float w2 = wd[(h+2)*128 + col];
        float w3 = wd[(h+3)*128 + col];
#pragma unroll
        for (int mi = 0; mi < K1_M; mi++){
            float4 iv = *reinterpret_cast<const float4*>(&in_s[mi][h]);
            acc[mi] = fmaf(iv.x, w0, acc[mi]);
            acc[mi] = fmaf(iv.y, w1, acc[mi]);
            acc[mi] = fmaf(iv.z, w2, acc[mi]);
            acc[mi] = fmaf(iv.w, w3, acc[mi]);
        }
    }
    const float bb = bd[col];
#pragma unroll
    for (int mi = 0; mi < K1_M; mi++) seq_s[mi][col] = acc[mi] + bb;
    __syncthreads();

    for (int t = tid; t < K1_M*64; t += 128){
        int mi = t >> 6, p = t & 63;
        int which = p >> 5, j = p & 31;
        int m = m0 + mi;
        float divf = (float)exp((double)j * -0.28782313662425574);
        float ang  = (float)m * divf;
        double ad  = (double)ang;
        float cv = (float)cos(ad), sv = (float)sin(ad);
        int base = which*64 + 2*j;
        float x0 = seq_s[mi][base], x1 = seq_s[mi][base+1];
        float* dst = which ? g_kw : g_qw;
        size_t o = ((size_t)b*NS + m) * D + 2*j;
        dst[o]   = x0*cv - x1*sv;
        dst[o+1] = x1*cv + x0*sv;
    }
}

// ---------------- K1b: ev ----------------
__global__ __launch_bounds__(64) void k1b_ev(const float* __restrict__ ein,
                                             const float* __restrict__ we,
                                             const float* __restrict__ be){
    __shared__ float e_s[H];
    const int c = blockIdx.x, tid = threadIdx.x;
    for (int i = tid; i < H; i += 64) e_s[i] = ein[(size_t)c*H + i];
    __syncthreads();
    float acc = 0.f;
#pragma unroll 1
    for (int h = 0; h < H; h += 4){
        float4 ev4 = *reinterpret_cast<const float4*>(&e_s[h]);
        acc = fmaf(ev4.x, we[(h+0)*D + tid], acc);
        acc = fmaf(ev4.y, we[(h+1)*D + tid], acc);
        acc = fmaf(ev4.z, we[(h+2)*D + tid], acc);
        acc = fmaf(ev4.w, we[(h+3)*D + tid], acc);
    }
    g_ev[c*D + tid] = acc + be[tid];
}

// ---------------- K_sum2: column sums, 8-way partial + deterministic combine ----------------
__global__ __launch_bounds__(512) void k_sum2(){
    __shared__ float red[8][64];
    const int which = blockIdx.x, b = blockIdx.y;
    const int tid = threadIdx.x, d = tid & 63, part = tid >> 6;
    const float* src = (which ? g_kw : g_qw) + (size_t)b*NS*D;
    float s = 0.f;
#pragma unroll 8
    for (int m = part; m < NS; m += 8) s += src[m*64 + d];
    red[part][d] = s;
    __syncthreads();
    if (tid < 64){
        float t = 0.f;
#pragma unroll
        for (int p = 0; p < 8; p++) t += red[p][tid];
        (which ? g_Ks : g_Qs)[b*64 + tid] = t;
    }
}

// ---------------- K15a: A = bf16(ev*q) ----------------
__global__ __launch_bounds__(256) void k15_A(){
    __shared__ float ev_s[D];
    const int bid = blockIdx.x;
    const int b = bid / 432, t = bid % 432;
    const int c = t >> 2, m0 = (t & 3) * 128;
    const int tid = threadIdx.x;
    if (tid < D) ev_s[tid] = g_ev[c*D + tid];
    __syncthreads();
    const float* q = g_qw + ((size_t)b*NS + m0)*D;
    __nv_bfloat16* dst = g_A + ((size_t)b*MROWS + (size_t)c*NS + m0)*D;
    for (int i = tid; i < 128*D; i += 256){
        int d = i & 63;
        dst[i] = __float2bfloat16(ev_s[d] * q[i]);
    }
}

// ---------------- K15b: Kb = bf16(kw) ----------------
__global__ __launch_bounds__(256) void k15_Kb(){
    int idx = blockIdx.x*256 + threadIdx.x;
    g_Kb[idx] = __float2bfloat16(g_kw[idx]);
}

// ================= GEMM tile helpers (M=128 x N=128, K=64) =================
__device__ __forceinline__ void load_tiles_128(char* smem, int b, int c, int m0, int n0, int tid){
    const uint4* pA = reinterpret_cast<const uint4*>(g_A);
    const size_t abase = ((size_t)b*MROWS + (size_t)c*NS + m0) * 8;
    const uint4* pB = reinterpret_cast<const uint4*>(g_Kb);
    const size_t bbase = ((size_t)b*NS + n0) * 8;
#pragma unroll
    for (int it = 0; it < 4; it++){
        int i = it*256 + tid;
        int row = i >> 3, c16 = i & 7;
        uint32_t so = swz128(row*128 + c16*16);
        *reinterpret_cast<uint4*>(smem + so)         = pA[abase + (size_t)row*8 + c16];
        *reinterpret_cast<uint4*>(smem + 16384 + so) = pB[bbase + (size_t)row*8 + c16];
    }
}
__device__ __forceinline__ void mainloop_128(uint32_t sbA, uint32_t sbB, int warp_m, int warp_n,
                                             int lane, float acc[4][4][4]){
#pragma unroll
    for (int kt = 0; kt < 4; kt++){
        uint32_t af[4][4], bf[4][2];
#pragma unroll
        for (int i = 0; i < 4; i++){
            int row = warp_m*64 + i*16 + (lane & 15);
            ldm_x4(af[i], sbA + swz128(row*128 + kt*32 + (lane >> 4)*16));
        }
#pragma unroll
        for (int j = 0; j < 4; j++){
            int row = warp_n*32 + j*8 + (lane & 7);
            ldm_x2(bf[j], sbB + swz128(row*128 + kt*32 + ((lane >> 3) & 1)*16));
        }
#pragma unroll
        for (int i = 0; i < 4; i++)
#pragma unroll
            for (int j = 0; j < 4; j++)
                mma16816(acc[i][j], af[i], bf[j]);
    }
}

// ---------------- KP1: einsum recompute -> per-channel max ----------------
__global__ __launch_bounds__(256) void kp1_chanmax(){
    __shared__ __align__(1024) char smem[32768];
    __shared__ float red_s[8];
    const uint32_t sbA = smem_u32(smem), sbB = sbA + 16384;
    const int tid = threadIdx.x, wid = tid >> 5, lane = tid & 31;
    const int warp_m = wid >> 2, warp_n = wid & 3;
    const int b = blockIdx.z, rt = blockIdx.y, n0 = blockIdx.x * 128;
    const int c = rt >> 2, m0 = (rt & 3) * 128;

    load_tiles_128(smem, b, c, m0, n0, tid);
    __syncthreads();

    float acc[4][4][4];
#pragma unroll
    for (int i = 0; i < 4; i++)
#pragma unroll
        for (int j = 0; j < 4; j++)
#pragma unroll
            for (int r = 0; r < 4; r++) acc[i][j][r] = 0.f;
    mainloop_128(sbA, sbB, warp_m, warp_n, lane, acc);

    float mx = -3.402823466e38f;
#pragma unroll
    for (int i = 0; i < 4; i++)
#pragma unroll
        for (int j = 0; j < 4; j++)
#pragma unroll
            for (int r = 0; r < 4; r++) mx = fmaxf(mx, acc[i][j][r]);
#pragma unroll
    for (int off = 16; off > 0; off >>= 1)
        mx = fmaxf(mx, __shfl_xor_sync(0xffffffffu, mx, off));
    if (lane == 0) red_s[wid] = mx;
    __syncthreads();
    if (tid == 0){
        float m2 = red_s[0];
#pragma unroll
        for (int w = 1; w < 8; w++) m2 = fmaxf(m2, red_s[w]);
        atomicMax(&g_chanMaxKey[b*C + c], fkey(m2));
    }
}

// ---------------- K3: scale + evS = sum_c scale_c * ev_c ----------------
__global__ __launch_bounds__(128) void k3_scale(const float* __restrict__ w1, const float* __restrict__ b1,
                                                const float* __restrict__ w2, const float* __restrict__ b2){
    __shared__ float avg_s[C], mx_s[C], hid_s[12], sc_s[C];
    const int tid = threadIdx.x;
    for (int b = 0; b < B; b++){
        if (tid < C){
            float s = 0.f;
            for (int d = 0; d < D; d++)
                s = fmaf(g_ev[tid*D + d], g_Qs[b*D + d]*g_Ks[b*D + d], s);
            avg_s[tid] = s * (1.f/262144.f);
            mx_s[tid]  = fkeyinv(g_chanMaxKey[b*C + tid]);
        }
        __syncthreads();
        if (tid < 12){
            int which = tid / 6, j = tid % 6;
            const float* v = which ? mx_s : avg_s;
            float h = b1[j];
            for (int c2 = 0; c2 < C; c2++) h = fmaf(v[c2], w1[c2*CH_HID + j], h);
            hid_s[tid] = fmaxf(h, 0.f);
        }
        __syncthreads();
        if (tid < C){
            float z = 2.f * b2[tid];
            for (int j = 0; j < CH_HID; j++)
                z = fmaf(hid_s[j] + hid_s[6+j], w2[j*C + tid], z);
            float sc = 1.f / (1.f + expf(-z));
            g_scale[b*C + tid] = sc;
            sc_s[tid] = sc;
        }
        __syncthreads();
        if (tid < D){
            float s = 0.f;
            for (int c2 = 0; c2 < C; c2++)
                s = fmaf(sc_s[c2], g_ev[c2*D + tid], s);
            g_evS[b*D + tid] = s;
        }
        __syncthreads();
    }
}

// ---------------- K_mean: compMean[m,n] = dot(evS, q_m o k_n)/C (exact factorization) ----------------
__global__ __launch_bounds__(256) void k_mean(){
    __shared__ float qe[8][68];
    __shared__ float ks[32][68];
    const int b = blockIdx.z, m0 = blockIdx.y*8, n0 = blockIdx.x*32, tid = threadIdx.x;

    // qe[m][d] = evS[d]*q[m,d]
    for (int i = tid; i < 8*64; i += 256){
        int mi = i >> 6, d = i & 63;
        qe[mi][d] = g_evS[b*64 + d] * g_qw[((size_t)b*NS + m0 + mi)*64 + d];
    }
    for (int i = tid; i < 32*64; i += 256){
        int ni = i >> 6, d = i & 63;
        ks[ni][d] = g_kw[((size_t)b*NS + n0 + ni)*64 + d];
    }
    __syncthreads();
    const int mi = tid >> 5, ni = tid & 31;
    float s = 0.f;
#pragma unroll
    for (int d = 0; d < 64; d += 4){
        float4 a = *reinterpret_cast<const float4*>(&qe[mi][d]);
        float4 kk = *reinterpret_cast<const float4*>(&ks[ni][d]);
        s = fmaf(a.x, kk.x, s); s = fmaf(a.y, kk.y, s);
        s = fmaf(a.z, kk.z, s); s = fmaf(a.w, kk.w, s);
    }
    g_compMean[((size_t)(b*NS + m0 + mi))*NS + n0 + ni] = s * (1.f/108.f);
}

// ---------------- Kmax: per-pixel max over channel subset (4-way split) ----------------
// tile m=64 x n=64, 256 thr (8 warps 4x2, warp 16x32); B frags preloaded; A double-buffered.
__global__ __launch_bounds__(256) void kmax_comp(){
    __shared__ __align__(1024) char smA[2][8192];
    __shared__ __align__(1024) char smB[8192];
    __shared__ float sc_s[C];
    const uint32_t sA0 = smem_u32(smA[0]), sA1 = smem_u32(smA[1]);
    const uint32_t sB  = smem_u32(smB);
    const int tid = threadIdx.x, wid = tid >> 5, lane = tid & 31;
    const int warp_m = wid >> 1, warp_n = wid & 1;
    const int z = blockIdx.z;                 // 0..7: b = z>>2, split = z&3
    const int b = z >> 2, split = z & 3;
    const int m0 = blockIdx.y * 64, n0 = blockIdx.x * 64;
    const int c0 = split * CSPL;

    if (tid < C) sc_s[tid] = g_scale[b*C + tid];
    // B tile: 64 rows x 128B
    {
        const uint4* pB = reinterpret_cast<const uint4*>(g_Kb);
        const size_t bbase = ((size_t)b*NS + n0) * 8;
#pragma unroll
        for (int it = 0; it < 2; it++){
            int i = it*256 + tid;              // 512 uint4
            int row = i >> 3, c16 = i & 7;
            *reinterpret_cast<uint4*>(smB + swz128(row*128 + c16*16)) = pB[bbase + (size_t)row*8 + c16];
        }
    }
    __syncthreads();

    uint32_t bf[4][4][2];
#pragma unroll
    for (int kt = 0; kt < 4; kt++)
#pragma unroll
        for (int j = 0; j < 4; j++){
            int row = warp_n*32 + j*8 + (lane & 7);
            ldm_x2(bf[kt][j], sB + swz128(row*128 + kt*32 + ((lane >> 3) & 1)*16));
        }

    const uint4* pA = reinterpret_cast<const uint4*>(g_A);
    const int r0 = tid >> 3, c16a = tid & 7;           // rows 0..31
    const int r1 = r0 + 32;                             // rows 32..63
    const uint32_t so0 = swz128(r0*128 + c16a*16);
    const uint32_t so1 = swz128(r1*128 + c16a*16);

    {
        const size_t abase = ((size_t)b*MROWS + (size_t)c0*NS + m0) * 8;
        *reinterpret_cast<uint4*>(smA[0] + so0) = pA[abase + (size_t)r0*8 + c16a];
        *reinterpret_cast<uint4*>(smA[0] + so1) = pA[abase + (size_t)r1*8 + c16a];
    }
    __syncthreads();

    float acc[4][4], mx[4][4];
#pragma unroll
    for (int j = 0; j < 4; j++)
#pragma unroll
        for (int r = 0; r < 4; r++){ acc[j][r] = 0.f; mx[j][r] = -3.402823466e38f; }

#pragma unroll 1
    for (int ci = 0; ci < CSPL; ci++){
        const int c = c0 + ci;
        uint4 pre0, pre1;
        if (ci + 1 < CSPL){
            const size_t abase = ((size_t)b*MROWS + (size_t)(c+1)*NS + m0) * 8;
            pre0 = pA[abase + (size_t)r0*8 + c16a];
            pre1 = pA[abase + (size_t)r1*8 + c16a];
        }
        const uint32_t sbA = (ci & 1) ? sA1 : sA0;
#pragma unroll
        for (int kt = 0; kt < 4; kt++){
            uint32_t af[4];
            int row = warp_m*16 + (lane & 15);
            ldm_x4(af, sbA + swz128(row*128 + kt*32 + (lane >> 4)*16));
#pragma unroll
            for (int j = 0; j < 4; j++)
                mma16816(acc[j], af, bf[kt][j]);
        }
        const float sc = sc_s[c];
#pragma unroll
        for (int j = 0; j < 4; j++)
#pragma unroll
            for (int r = 0; r < 4; r++){
                mx[j][r] = fmaxf(mx[j][r], acc[j][r] * sc);
                acc[j][r] = 0.f;
            }
        if (ci + 1 < CSPL){
            char* dst = (ci & 1) ? smA[0] : smA[1];
            *reinterpret_cast<uint4*>(dst + so0) = pre0;
            *reinterpret_cast<uint4*>(dst + so1) = pre1;
            __syncthreads();
        }
    }

    float* outb = g_cmax[split];
#pragma unroll
    for (int j = 0; j < 4; j++){
        int gm0 = m0 + warp_m*16 + (lane >> 2);
        int gn  = n0 + warp_n*32 + j*8 + (lane & 3)*2;
        size_t p0 = ((size_t)(b*NS + gm0))*NS + gn;
        size_t p1 = ((size_t)(b*NS + gm0 + 8))*NS + gn;
        *reinterpret_cast<float2*>(&outb[p0]) = make_float2(mx[j][0], mx[j][1]);
        *reinterpret_cast<float2*>(&outb[p1]) = make_float2(mx[j][2], mx[j][3]);
    }
}

// ---------------- K5: 7x7 conv + sigmoid (combines 4 max splits) ----------------
#define CT 16
__global__ __launch_bounds__(256) void k5_conv(const float* __restrict__ cw){
    __shared__ float smax[CT+6][CT+6];
    __shared__ float smean[CT+6][CT+6];
    __shared__ float w_s[98];
    const int b = blockIdx.z, m0 = blockIdx.y*CT, n0 = blockIdx.x*CT, tid = threadIdx.x;
    if (tid < 98) w_s[tid] = cw[tid];
    for (int i = tid; i < (CT+6)*(CT+6); i += 256){
        int r = i / (CT+6), cc = i % (CT+6);
        int gm = m0 + r - 3, gn = n0 + cc - 3;
        float a = 0.f, mn = 0.f;
        if (gm >= 0 && gm < NS && gn >= 0 && gn < NS){
            size_t gi = (size_t)(b*NS + gm)*NS + gn;
            a = fmaxf(fmaxf(g_cmax[0][gi], g_cmax[1][gi]),
                      fmaxf(g_cmax[2][gi], g_cmax[3][gi]));
            mn = g_compMean[gi];
        }
        smax[r][cc] = a; smean[r][cc] = mn;
    }
    __syncthreads();
    const int ty = tid / CT, tx = tid % CT;
    float acc = 0.f;
#pragma unroll
    for (int kh = 0; kh < 7; kh++)
#pragma unroll
        for (int kw = 0; kw < 7; kw++){
            acc = fmaf(smax[ty+kh][tx+kw],  w_s[kh*7 + kw],      acc);
            acc = fmaf(smean[ty+kh][tx+kw], w_s[49 + kh*7 + kw], acc);
        }
    acc *= 0.9999950000374997f;
    g_sig[(size_t)(b*NS + m0 + ty)*NS + n0 + tx] = 1.f / (1.f + expf(-acc));
}

// ---------------- KP3: einsum recompute -> fused final epilogue -> out ----------------
__global__ __launch_bounds__(256) void kp3_final(float* __restrict__ out, const int* __restrict__ mask){
    __shared__ __align__(1024) char smem[32768];
    __shared__ int mrow_s[128], mcol_s[128];
    const uint32_t sbA = smem_u32(smem), sbB = sbA + 16384;
    const int tid = threadIdx.x, wid = tid >> 5, lane = tid & 31;
    const int warp_m = wid >> 2, warp_n = wid & 3;
    const int b = blockIdx.z, rt = blockIdx.y, n0 = blockIdx.x * 128;
    const int c = rt >> 2, m0 = (rt & 3) * 128;

    load_tiles_128(smem, b, c, m0, n0, tid);
    if (tid < 128){
        mrow_s[tid] = mask[b*NS + m0 + tid];
        mcol_s[tid] = mask[b*NS + n0 + tid];
    }
    __syncthreads();

    float acc[4][4][4];
#pragma unroll
    for (int i = 0; i < 4; i++)
#pragma unroll
        for (int j = 0; j < 4; j++)
#pragma unroll
            for (int r = 0; r < 4; r++) acc[i][j][r] = 0.f;
    mainloop_128(sbA, sbB, warp_m, warp_n, lane, acc);

    const float sc = g_scale[b*C + c];
    const size_t obase = ((size_t)(b*C + c)*NS + m0)*NS + n0;
    const float NEGINF = __int_as_float(0xff800000);
#pragma unroll
    for (int i = 0; i < 4; i++){
        int lrow0 = warp_m*64 + i*16 + (lane >> 2);
#pragma unroll
        for (int j = 0; j < 4; j++){
            int lcol = warp_n*32 + j*8 + (lane & 3)*2;
            int gn = n0 + lcol;
            int mc0 = mcol_s[lcol], mc1 = mcol_s[lcol+1];
#pragma unroll
            for (int h = 0; h < 2; h++){
                int lrow = lrow0 + h*8;
                int gm = m0 + lrow;
                float2 sg = *reinterpret_cast<const float2*>(&g_sig[((size_t)(b*NS + gm))*NS + gn]);
                int mr = mrow_s[lrow];
                float y0 = acc[i][j][2*h]   * fmaf(sc, sg.x, 1.f);
                float y1 = acc[i][j][2*h+1] * fmaf(sc, sg.y, 1.f);
                if (gm > gn)     y0 -= 1e12f;
                if (gm > gn + 1) y1 -= 1e12f;
                if (mr == 0 || mc0 == 0) y0 = NEGINF;
                if (mr == 0 || mc1 == 0) y1 = NEGINF;
                *reinterpret_cast<float2*>(&out[obase + (size_t)lrow*NS + lcol]) =
                    make_float2(y0 * 0.125f, y1 * 0.125f);
            }
        }
    }
}

// ---------------- launcher ----------------
extern "C" void kernel_launch(void* const* d_in, const int* in_sizes, int n_in,
                              void* d_out, int out_size){
    (void)in_sizes; (void)n_in; (void)out_size;
    const float* inputs       = (const float*)d_in[0];
    const float* event_inputs = (const float*)d_in[1];
    const int*   mask         = (const int*)  d_in[2];
    const float* w_dense      = (const float*)d_in[3];
    const float* b_dense      = (const float*)d_in[4];
    const float* w_event      = (const float*)d_in[5];
    const float* b_event      = (const float*)d_in[6];
    const float* mlp_w1       = (const float*)d_in[7];
    const float* mlp_b1       = (const float*)d_in[8];
    const float* mlp_w2       = (const float*)d_in[9];
    const float* mlp_b2       = (const float*)d_in[10];
    const float* conv_w       = (const float*)d_in[11];
    float* out = (float*)d_out;

    k0_init<<<1, 256>>>();
    k1_qk<<<dim3(64, 2), 128>>>(inputs, w_dense, b_dense);
    k1b_ev<<<108, 64>>>(event_inputs, w_event, b_event);
    k_sum2<<<dim3(2, 2), 512>>>();
    k15_A<<<864, 256>>>();
    k15_Kb<<<256, 256>>>();
    kp1_chanmax<<<dim3(4, 432, 2), 256>>>();
    k3_scale<<<1, 128>>>(mlp_w1, mlp_b1, mlp_w2, mlp_b2);
    k_mean<<<dim3(16, 64, 2), 256>>>();
    kmax_comp<<<dim3(8, 8, 8), 256>>>();
    k5_conv<<<dim3(32, 32, 2), 256>>>(conv_w);
    kp3_final<<<dim3(4, 432, 2), 256>>>(out, mask);
}

// round 10
// speedup vs baseline: 1.0049x; 1.0049x over previous
#include <cuda_runtime.h>
#include <cuda_bf16.h>
#include <cstdint>
#include <math.h>

#define B   2
#define NS  512
#define H   768
#define C   108
#define D   64
#define PIX (NS*NS)
#define CH_HID 6
#define MROWS (C*NS)
#define NSPLIT 4
#define CSPL  (C/NSPLIT)     // 27

// ---------------- device scratch ----------------
__device__ float          g_qw[B*NS*D];
__device__ float          g_kw[B*NS*D];
__device__ float          g_ev[C*D];
__device__ float          g_Qs[B*D];
__device__ float          g_Ks[B*D];
__device__ float          g_evS[B*D];
__device__ unsigned       g_chanMaxKey[B*C];
__device__ float          g_scale[B*C];
__device__ float          g_cmax[NSPLIT][B*PIX];   // 8 MB: per-split pixel max
__device__ float          g_compMean[B*PIX];
__device__ float          g_sig[B*PIX];
__device__ __nv_bfloat16  g_A[B*MROWS*D];          // 14.2 MB: bf16(ev*q)
__device__ __nv_bfloat16  g_Kb[B*NS*D];            // bf16(k)

__device__ __forceinline__ unsigned fkey(float f){
    unsigned u = __float_as_uint(f);
    return (u & 0x80000000u) ? ~u : (u | 0x80000000u);
}
__device__ __forceinline__ float fkeyinv(unsigned k){
    return __uint_as_float((k & 0x80000000u) ? (k & 0x7fffffffu) : ~k);
}
__device__ __forceinline__ uint32_t smem_u32(const void* p){
    uint32_t a;
    asm("{ .reg .u64 t; cvta.to.shared.u64 t, %1; cvt.u32.u64 %0, t; }" : "=r"(a) : "l"(p));
    return a;
}
__device__ __forceinline__ uint32_t swz128(uint32_t off){ return off ^ ((off >> 3) & 0x70); }

// ---- warp-level bf16 tensor core ops (baseline PTX; works on .target sm_100) ----
__device__ __forceinline__ void ldm_x4(uint32_t* r, uint32_t addr){
    asm volatile("ldmatrix.sync.aligned.m8n8.x4.shared.b16 {%0,%1,%2,%3}, [%4];"
        : "=r"(r[0]), "=r"(r[1]), "=r"(r[2]), "=r"(r[3]) : "r"(addr));
}
__device__ __forceinline__ void ldm_x2(uint32_t* r, uint32_t addr){
    asm volatile("ldmatrix.sync.aligned.m8n8.x2.shared.b16 {%0,%1}, [%2];"
        : "=r"(r[0]), "=r"(r[1]) : "r"(addr));
}
__device__ __forceinline__ void mma16816(float* c, const uint32_t* a, const uint32_t* b){
    asm volatile("mma.sync.aligned.m16n8k16.row.col.f32.bf16.bf16.f32 "
        "{%0,%1,%2,%3}, {%4,%5,%6,%7}, {%8,%9}, {%0,%1,%2,%3};"
        : "+f"(c[0]), "+f"(c[1]), "+f"(c[2]), "+f"(c[3])
        : "r"(a[0]), "r"(a[1]), "r"(a[2]), "r"(a[3]), "r"(b[0]), "r"(b[1]));
}

// ---------------- K0 ----------------
__global__ void k0_init(){
    int i = threadIdx.x;
    if (i < B*C) g_chanMaxKey[i] = 0u;
}

// ---------------- K1: dense + RoPE ----------------
#define K1_M 8
__global__ __launch_bounds__(128) void k1_qk(const float* __restrict__ inp,
                                             const float* __restrict__ wd,
                                             const float* __restrict__ bd){
    __shared__ float in_s[K1_M][H];
    __shared__ float seq_s[K1_M][128];
    const int b = blockIdx.y, m0 = blockIdx.x * K1_M, tid = threadIdx.x;

    const float* src = inp + ((size_t)b*NS + m0) * H;
    for (int i = tid; i < K1_M*H; i += 128) in_s[i/H][i%H] = src[i];
    __syncthreads();

    const int col = tid;
    float acc[K1_M];
#pragma unroll
    for (int mi = 0; mi < K1_M; mi++) acc[mi] = 0.f;
#pragma unroll 1
    for (int h = 0; h < H; h += 4){
        float w0 = wd[(h+0)*128 + col];
        float w1 = wd[(h+1)*128 + col];
        float w2 = wd[(h+2)*128 + col];
        float w3 = wd[(h+3)*128 + col];
#pragma unroll
        for (int mi = 0; mi < K1_M; mi++){
            float4 iv = *reinterpret_cast<const float4*>(&in_s[mi][h]);
            acc[mi] = fmaf(iv.x, w0, acc[mi]);
            acc[mi] = fmaf(iv.y, w1, acc[mi]);
            acc[mi] = fmaf(iv.z, w2, acc[mi]);
            acc[mi] = fmaf(iv.w, w3, acc[mi]);
        }
    }
    const float bb = bd[col];
#pragma unroll
    for (int mi = 0; mi < K1_M; mi++) seq_s[mi][col] = acc[mi] + bb;
    __syncthreads();

    for (int t = tid; t < K1_M*64; t += 128){
        int mi = t >> 6, p = t & 63;
        int which = p >> 5, j = p & 31;
        int m = m0 + mi;
        float divf = (float)exp((double)j * -0.28782313662425574);
        float ang  = (float)m * divf;
        double ad  = (double)ang;
        float cv = (float)cos(ad), sv = (float)sin(ad);
        int base = which*64 + 2*j;
        float x0 = seq_s[mi][base], x1 = seq_s[mi][base+1];
        float* dst = which ? g_kw : g_qw;
        size_t o = ((size_t)b*NS + m) * D + 2*j;
        dst[o]   = x0*cv - x1*sv;
        dst[o+1] = x1*cv + x0*sv;
    }
}

// ---------------- K1b: ev ----------------
__global__ __launch_bounds__(64) void k1b_ev(const float* __restrict__ ein,
                                             const float* __restrict__ we,
                                             const float* __restrict__ be){
    __shared__ float e_s[H];
    const int c = blockIdx.x, tid = threadIdx.x;
    for (int i = tid; i < H; i += 64) e_s[i] = ein[(size_t)c*H + i];
    __syncthreads();
    float acc = 0.f;
#pragma unroll 1
    for (int h = 0; h < H; h += 4){
        float4 ev4 = *reinterpret_cast<const float4*>(&e_s[h]);
        acc = fmaf(ev4.x, we[(h+0)*D + tid], acc);
        acc = fmaf(ev4.y, we[(h+1)*D + tid], acc);
        acc = fmaf(ev4.z, we[(h+2)*D + tid], acc);
        acc = fmaf(ev4.w, we[(h+3)*D + tid], acc);
    }
    g_ev[c*D + tid] = acc + be[tid];
}

// ---------------- K_sum2: column sums, 8-way partial + deterministic combine ----------------
__global__ __launch_bounds__(512) void k_sum2(){
    __shared__ float red[8][64];
    const int which = blockIdx.x, b = blockIdx.y;
    const int tid = threadIdx.x, d = tid & 63, part = tid >> 6;
    const float* src = (which ? g_kw : g_qw) + (size_t)b*NS*D;
    float s = 0.f;
#pragma unroll 8
    for (int m = part; m < NS; m += 8) s += src[m*64 + d];
    red[part][d] = s;
    __syncthreads();
    if (tid < 64){
        float t = 0.f;
#pragma unroll
        for (int p = 0; p < 8; p++) t += red[p][tid];
        (which ? g_Ks : g_Qs)[b*64 + tid] = t;
    }
}

// ---------------- K15a: A = bf16(ev*q) ----------------
__global__ __launch_bounds__(256) void k15_A(){
    __shared__ float ev_s[D];
    const int bid = blockIdx.x;
    const int b = bid / 432, t = bid % 432;
    const int c = t >> 2, m0 = (t & 3) * 128;
    const int tid = threadIdx.x;
    if (tid < D) ev_s[tid] = g_ev[c*D + tid];
    __syncthreads();
    const float* q = g_qw + ((size_t)b*NS + m0)*D;
    __nv_bfloat16* dst = g_A + ((size_t)b*MROWS + (size_t)c*NS + m0)*D;
    for (int i = tid; i < 128*D; i += 256){
        int d = i & 63;
        dst[i] = __float2bfloat16(ev_s[d] * q[i]);
    }
}

// ---------------- K15b: Kb = bf16(kw) ----------------
__global__ __launch_bounds__(256) void k15_Kb(){
    int idx = blockIdx.x*256 + threadIdx.x;
    g_Kb[idx] = __float2bfloat16(g_kw[idx]);
}

// ================= GEMM tile helpers (M=128 x N=128, K=64) =================
__device__ __forceinline__ void load_tiles_128(char* smem, int b, int c, int m0, int n0, int tid){
    const uint4* pA = reinterpret_cast<const uint4*>(g_A);
    const size_t abase = ((size_t)b*MROWS + (size_t)c*NS + m0) * 8;
    const uint4* pB = reinterpret_cast<const uint4*>(g_Kb);
    const size_t bbase = ((size_t)b*NS + n0) * 8;
#pragma unroll
    for (int it = 0; it < 4; it++){
        int i = it*256 + tid;
        int row = i >> 3, c16 = i & 7;
        uint32_t so = swz128(row*128 + c16*16);
        *reinterpret_cast<uint4*>(smem + so)         = pA[abase + (size_t)row*8 + c16];
        *reinterpret_cast<uint4*>(smem + 16384 + so) = pB[bbase + (size_t)row*8 + c16];
    }
}
__device__ __forceinline__ void mainloop_128(uint32_t sbA, uint32_t sbB, int warp_m, int warp_n,
                                             int lane, float acc[4][4][4]){
#pragma unroll
    for (int kt = 0; kt < 4; kt++){
        uint32_t af[4][4], bf[4][2];
#pragma unroll
        for (int i = 0; i < 4; i++){
            int row = warp_m*64 + i*16 + (lane & 15);
            ldm_x4(af[i], sbA + swz128(row*128 + kt*32 + (lane >> 4)*16));
        }
#pragma unroll
        for (int j = 0; j < 4; j++){
            int row = warp_n*32 + j*8 + (lane & 7);
            ldm_x2(bf[j], sbB + swz128(row*128 + kt*32 + ((lane >> 3) & 1)*16));
        }
#pragma unroll
        for (int i = 0; i < 4; i++)
#pragma unroll
            for (int j = 0; j < 4; j++)
                mma16816(acc[i][j], af[i], bf[j]);
    }
}

// ---------------- KP1: einsum recompute -> per-channel max ----------------
__global__ __launch_bounds__(256) void kp1_chanmax(){
    __shared__ __align__(1024) char smem[32768];
    __shared__ float red_s[8];
    const uint32_t sbA = smem_u32(smem), sbB = sbA + 16384;
    const int tid = threadIdx.x, wid = tid >> 5, lane = tid & 31;
    const int warp_m = wid >> 2, warp_n = wid & 3;
    const int b = blockIdx.z, rt = blockIdx.y, n0 = blockIdx.x * 128;
    const int c = rt >> 2, m0 = (rt & 3) * 128;

    load_tiles_128(smem, b, c, m0, n0, tid);
    __syncthreads();

    float acc[4][4][4];
#pragma unroll
    for (int i = 0; i < 4; i++)
#pragma unroll
        for (int j = 0; j < 4; j++)
#pragma unroll
            for (int r = 0; r < 4; r++) acc[i][j][r] = 0.f;
    mainloop_128(sbA, sbB, warp_m, warp_n, lane, acc);

    float mx = -3.402823466e38f;
#pragma unroll
    for (int i = 0; i < 4; i++)
#pragma unroll
        for (int j = 0; j < 4; j++)
#pragma unroll
            for (int r = 0; r < 4; r++) mx = fmaxf(mx, acc[i][j][r]);
#pragma unroll
    for (int off = 16; off > 0; off >>= 1)
        mx = fmaxf(mx, __shfl_xor_sync(0xffffffffu, mx, off));
    if (lane == 0) red_s[wid] = mx;
    __syncthreads();
    if (tid == 0){
        float m2 = red_s[0];
#pragma unroll
        for (int w = 1; w < 8; w++) m2 = fmaxf(m2, red_s[w]);
        atomicMax(&g_chanMaxKey[b*C + c], fkey(m2));
    }
}

// ---------------- K3: scale + evS = sum_c scale_c * ev_c ----------------
__global__ __launch_bounds__(128) void k3_scale(const float* __restrict__ w1, const float* __restrict__ b1,
                                                const float* __restrict__ w2, const float* __restrict__ b2){
    __shared__ float avg_s[C], mx_s[C], hid_s[12], sc_s[C];
    const int tid = threadIdx.x;
    for (int b = 0; b < B; b++){
        if (tid < C){
            float s = 0.f;
            for (int d = 0; d < D; d++)
                s = fmaf(g_ev[tid*D + d], g_Qs[b*D + d]*g_Ks[b*D + d], s);
            avg_s[tid] = s * (1.f/262144.f);
            mx_s[tid]  = fkeyinv(g_chanMaxKey[b*C + tid]);
        }
        __syncthreads();
        if (tid < 12){
            int which = tid / 6, j = tid % 6;
            const float* v = which ? mx_s : avg_s;
            float h = b1[j];
            for (int c2 = 0; c2 < C; c2++) h = fmaf(v[c2], w1[c2*CH_HID + j], h);
            hid_s[tid] = fmaxf(h, 0.f);
        }
        __syncthreads();
        if (tid < C){
            float z = 2.f * b2[tid];
            for (int j = 0; j < CH_HID; j++)
                z = fmaf(hid_s[j] + hid_s[6+j], w2[j*C + tid], z);
            float sc = 1.f / (1.f + expf(-z));
            g_scale[b*C + tid] = sc;
            sc_s[tid] = sc;
        }
        __syncthreads();
        if (tid < D){
            float s = 0.f;
            for (int c2 = 0; c2 < C; c2++)
                s = fmaf(sc_s[c2], g_ev[c2*D + tid], s);
            g_evS[b*D + tid] = s;
        }
        __syncthreads();
    }
}

// ---------------- K_mean: compMean[m,n] = dot(evS, q_m o k_n)/C (exact factorization) ----------------
__global__ __launch_bounds__(256) void k_mean(){
    __shared__ float qe[8][68];
    __shared__ float ks[32][68];
    const int b = blockIdx.z, m0 = blockIdx.y*8, n0 = blockIdx.x*32, tid = threadIdx.x;

    // qe[m][d] = evS[d]*q[m,d]
    for (int i = tid; i < 8*64; i += 256){
        int mi = i >> 6, d = i & 63;
        qe[mi][d] = g_evS[b*64 + d] * g_qw[((size_t)b*NS + m0 + mi)*64 + d];
    }
    for (int i = tid; i < 32*64; i += 256){
        int ni = i >> 6, d = i & 63;
        ks[ni][d] = g_kw[((size_t)b*NS + n0 + ni)*64 + d];
    }
    __syncthreads();
    const int mi = tid >> 5, ni = tid & 31;
    float s = 0.f;
#pragma unroll
    for (int d = 0; d < 64; d += 4){
        float4 a = *reinterpret_cast<const float4*>(&qe[mi][d]);
        float4 kk = *reinterpret_cast<const float4*>(&ks[ni][d]);
        s = fmaf(a.x, kk.x, s); s = fmaf(a.y, kk.y, s);
        s = fmaf(a.z, kk.z, s); s = fmaf(a.w, kk.w, s);
    }
    g_compMean[((size_t)(b*NS + m0 + mi))*NS + n0 + ni] = s * (1.f/108.f);
}

// ---------------- Kmax: per-pixel max over channel subset (4-way split) ----------------
// tile m=64 x n=64, 256 thr (8 warps 4x2, warp 16x32); B frags preloaded; A double-buffered.
__global__ __launch_bounds__(256) void kmax_comp(){
    __shared__ __align__(1024) char smA[2][8192];
    __shared__ __align__(1024) char smB[8192];
    __shared__ float sc_s[C];
    const uint32_t sA0 = smem_u32(smA[0]), sA1 = smem_u32(smA[1]);
    const uint32_t sB  = smem_u32(smB);
    const int tid = threadIdx.x, wid = tid >> 5, lane = tid & 31;
    const int warp_m = wid >> 1, warp_n = wid & 1;
    const int z = blockIdx.z;                 // 0..7: b = z>>2, split = z&3
    const int b = z >> 2, split = z & 3;
    const int m0 = blockIdx.y * 64, n0 = blockIdx.x * 64;
    const int c0 = split * CSPL;

    if (tid < C) sc_s[tid] = g_scale[b*C + tid];
    // B tile: 64 rows x 128B
    {
        const uint4* pB = reinterpret_cast<const uint4*>(g_Kb);
        const size_t bbase = ((size_t)b*NS + n0) * 8;
#pragma unroll
        for (int it = 0; it < 2; it++){
            int i = it*256 + tid;              // 512 uint4
            int row = i >> 3, c16 = i & 7;
            *reinterpret_cast<uint4*>(smB + swz128(row*128 + c16*16)) = pB[bbase + (size_t)row*8 + c16];
        }
    }
    __syncthreads();

    uint32_t bf[4][4][2];
#pragma unroll
    for (int kt = 0; kt < 4; kt++)
#pragma unroll
        for (int j = 0; j < 4; j++){
            int row = warp_n*32 + j*8 + (lane & 7);
            ldm_x2(bf[kt][j], sB + swz128(row*128 + kt*32 + ((lane >> 3) & 1)*16));
        }

    const uint4* pA = reinterpret_cast<const uint4*>(g_A);
    const int r0 = tid >> 3, c16a = tid & 7;           // rows 0..31
    const int r1 = r0 + 32;                             // rows 32..63
    const uint32_t so0 = swz128(r0*128 + c16a*16);
    const uint32_t so1 = swz128(r1*128 + c16a*16);

    {
        const size_t abase = ((size_t)b*MROWS + (size_t)c0*NS + m0) * 8;
        *reinterpret_cast<uint4*>(smA[0] + so0) = pA[abase + (size_t)r0*8 + c16a];
        *reinterpret_cast<uint4*>(smA[0] + so1) = pA[abase + (size_t)r1*8 + c16a];
    }
    __syncthreads();

    float acc[4][4], mx[4][4];
#pragma unroll
    for (int j = 0; j < 4; j++)
#pragma unroll
        for (int r = 0; r < 4; r++){ acc[j][r] = 0.f; mx[j][r] = -3.402823466e38f; }

#pragma unroll 1
    for (int ci = 0; ci < CSPL; ci++){
        const int c = c0 + ci;
        uint4 pre0, pre1;
        if (ci + 1 < CSPL){
            const size_t abase = ((size_t)b*MROWS + (size_t)(c+1)*NS + m0) * 8;
            pre0 = pA[abase + (size_t)r0*8 + c16a];
            pre1 = pA[abase + (size_t)r1*8 + c16a];
        }
        const uint32_t sbA = (ci & 1) ? sA1 : sA0;
#pragma unroll
        for (int kt = 0; kt < 4; kt++){
            uint32_t af[4];
            int row = warp_m*16 + (lane & 15);
            ldm_x4(af, sbA + swz128(row*128 + kt*32 + (lane >> 4)*16));
#pragma unroll
            for (int j = 0; j < 4; j++)
                mma16816(acc[j], af, bf[kt][j]);
        }
        const float sc = sc_s[c];
#pragma unroll
        for (int j = 0; j < 4; j++)
#pragma unroll
            for (int r = 0; r < 4; r++){
                mx[j][r] = fmaxf(mx[j][r], acc[j][r] * sc);
                acc[j][r] = 0.f;
            }
        if (ci + 1 < CSPL){
            char* dst = (ci & 1) ? smA[0] : smA[1];
            *reinterpret_cast<uint4*>(dst + so0) = pre0;
            *reinterpret_cast<uint4*>(dst + so1) = pre1;
            __syncthreads();
        }
    }

    float* outb = g_cmax[split];
#pragma unroll
    for (int j = 0; j < 4; j++){
        int gm0 = m0 + warp_m*16 + (lane >> 2);
        int gn  = n0 + warp_n*32 + j*8 + (lane & 3)*2;
        size_t p0 = ((size_t)(b*NS + gm0))*NS + gn;
        size_t p1 = ((size_t)(b*NS + gm0 + 8))*NS + gn;
        *reinterpret_cast<float2*>(&outb[p0]) = make_float2(mx[j][0], mx[j][1]);
        *reinterpret_cast<float2*>(&outb[p1]) = make_float2(mx[j][2], mx[j][3]);
    }
}

// ---------------- K5: 7x7 conv + sigmoid (combines 4 max splits) ----------------
#define CT 16
__global__ __launch_bounds__(256) void k5_conv(const float* __restrict__ cw){
    __shared__ float smax[CT+6][CT+6];
    __shared__ float smean[CT+6][CT+6];
    __shared__ float w_s[98];
    const int b = blockIdx.z, m0 = blockIdx.y*CT, n0 = blockIdx.x*CT, tid = threadIdx.x;
    if (tid < 98) w_s[tid] = cw[tid];
    for (int i = tid; i < (CT+6)*(CT+6); i += 256){
        int r = i / (CT+6), cc = i % (CT+6);
        int gm = m0 + r - 3, gn = n0 + cc - 3;
        float a = 0.f, mn = 0.f;
        if (gm >= 0 && gm < NS && gn >= 0 && gn < NS){
            size_t gi = (size_t)(b*NS + gm)*NS + gn;
            a = fmaxf(fmaxf(g_cmax[0][gi], g_cmax[1][gi]),
                      fmaxf(g_cmax[2][gi], g_cmax[3][gi]));
            mn = g_compMean[gi];
        }
        smax[r][cc] = a; smean[r][cc] = mn;
    }
    __syncthreads();
    const int ty = tid / CT, tx = tid % CT;
    float acc = 0.f;
#pragma unroll
    for (int kh = 0; kh < 7; kh++)
#pragma unroll
        for (int kw = 0; kw < 7; kw++){
            acc = fmaf(smax[ty+kh][tx+kw],  w_s[kh*7 + kw],      acc);
            acc = fmaf(smean[ty+kh][tx+kw], w_s[49 + kh*7 + kw], acc);
        }
    acc *= 0.9999950000374997f;
    g_sig[(size_t)(b*NS + m0 + ty)*NS + n0 + tx] = 1.f / (1.f + expf(-acc));
}

// ---------------- KP3: einsum recompute -> fused final epilogue -> out ----------------
__global__ __launch_bounds__(256) void kp3_final(float* __restrict__ out, const int* __restrict__ mask){
    __shared__ __align__(1024) char smem[32768];
    __shared__ int mrow_s[128], mcol_s[128];
    const uint32_t sbA = smem_u32(smem), sbB = sbA + 16384;
    const int tid = threadIdx.x, wid = tid >> 5, lane = tid & 31;
    const int warp_m = wid >> 2, warp_n = wid & 3;
    const int b = blockIdx.z, rt = blockIdx.y, n0 = blockIdx.x * 128;
    const int c = rt >> 2, m0 = (rt & 3) * 128;

    load_tiles_128(smem, b, c, m0, n0, tid);
    if (tid < 128){
        mrow_s[tid] = mask[b*NS + m0 + tid];
        mcol_s[tid] = mask[b*NS + n0 + tid];
    }
    __syncthreads();

    float acc[4][4][4];
#pragma unroll
    for (int i = 0; i < 4; i++)
#pragma unroll
        for (int j = 0; j < 4; j++)
#pragma unroll
            for (int r = 0; r < 4; r++) acc[i][j][r] = 0.f;
    mainloop_128(sbA, sbB, warp_m, warp_n, lane, acc);

    const float sc = g_scale[b*C + c];
    const size_t obase = ((size_t)(b*C + c)*NS + m0)*NS + n0;
    const float NEGINF = __int_as_float(0xff800000);
#pragma unroll
    for (int i = 0; i < 4; i++){
        int lrow0 = warp_m*64 + i*16 + (lane >> 2);
#pragma unroll
        for (int j = 0; j < 4; j++){
            int lcol = warp_n*32 + j*8 + (lane & 3)*2;
            int gn = n0 + lcol;
            int mc0 = mcol_s[lcol], mc1 = mcol_s[lcol+1];
#pragma unroll
            for (int h = 0; h < 2; h++){
                int lrow = lrow0 + h*8;
                int gm = m0 + lrow;
                float2 sg = *reinterpret_cast<const float2*>(&g_sig[((size_t)(b*NS + gm))*NS + gn]);
                int mr = mrow_s[lrow];
                float y0 = acc[i][j][2*h]   * fmaf(sc, sg.x, 1.f);
                float y1 = acc[i][j][2*h+1] * fmaf(sc, sg.y, 1.f);
                if (gm > gn)     y0 -= 1e12f;
                if (gm > gn + 1) y1 -= 1e12f;
                if (mr == 0 || mc0 == 0) y0 = NEGINF;
                if (mr == 0 || mc1 == 0) y1 = NEGINF;
                *reinterpret_cast<float2*>(&out[obase + (size_t)lrow*NS + lcol]) =
                    make_float2(y0 * 0.125f, y1 * 0.125f);
            }
        }
    }
}

// ---------------- launcher ----------------
extern "C" void kernel_launch(void* const* d_in, const int* in_sizes, int n_in,
                              void* d_out, int out_size){
    (void)in_sizes; (void)n_in; (void)out_size;
    const float* inputs       = (const float*)d_in[0];
    const float* event_inputs = (const float*)d_in[1];
    const int*   mask         = (const int*)  d_in[2];
    const float* w_dense      = (const float*)d_in[3];
    const float* b_dense      = (const float*)d_in[4];
    const float* w_event      = (const float*)d_in[5];
    const float* b_event      = (const float*)d_in[6];
    const float* mlp_w1       = (const float*)d_in[7];
    const float* mlp_b1       = (const float*)d_in[8];
    const float* mlp_w2       = (const float*)d_in[9];
    const float* mlp_b2       = (const float*)d_in[10];
    const float* conv_w       = (const float*)d_in[11];
    float* out = (float*)d_out;

    k0_init<<<1, 256>>>();
    k1_qk<<<dim3(64, 2), 128>>>(inputs, w_dense, b_dense);
    k1b_ev<<<108, 64>>>(event_inputs, w_event, b_event);
    k_sum2<<<dim3(2, 2), 512>>>();
    k15_A<<<864, 256>>>();
    k15_Kb<<<256, 256>>>();
    kp1_chanmax<<<dim3(4, 432, 2), 256>>>();
    k3_scale<<<1, 128>>>(mlp_w1, mlp_b1, mlp_w2, mlp_b2);
    k_mean<<<dim3(16, 64, 2), 256>>>();
    kmax_comp<<<dim3(8, 8, 8), 256>>>();
    k5_conv<<<dim3(32, 32, 2), 256>>>(conv_w);
    kp3_final<<<dim3(4, 432, 2), 256>>>(out, mask);
}

// round 11
// speedup vs baseline: 1.0779x; 1.0726x over previous
#include <cuda_runtime.h>
#include <cuda_bf16.h>
#include <cstdint>
#include <math.h>

#define B   2
#define NS  512
#define H   768
#define C   108
#define D   64
#define PIX (NS*NS)
#define CH_HID 6

// ---------------- device scratch ----------------
__device__ float          g_qw[B*NS*D];
__device__ float          g_kw[B*NS*D];
__device__ float          g_ev[C*D];
__device__ __nv_bfloat16  g_evb[C*D];        // bf16(ev)
__device__ __nv_bfloat16  g_evSb[B*D];       // bf16(sum_c scale_c*ev_c)
__device__ float          g_Qs[B*D];
__device__ float          g_Ks[B*D];
__device__ unsigned       g_chanMaxKey[B*C];
__device__ float          g_scale[B*C];
__device__ float          g_compMax[B*PIX];
__device__ float          g_compMean[B*PIX];
__device__ float          g_sig[B*PIX];
__device__ __nv_bfloat16  g_Qb[B*NS*D];      // bf16(q) 128KB
__device__ __nv_bfloat16  g_Kb[B*NS*D];      // bf16(k) 128KB

__device__ __forceinline__ unsigned fkey(float f){
    unsigned u = __float_as_uint(f);
    return (u & 0x80000000u) ? ~u : (u | 0x80000000u);
}
__device__ __forceinline__ float fkeyinv(unsigned k){
    return __uint_as_float((k & 0x80000000u) ? (k & 0x7fffffffu) : ~k);
}
__device__ __forceinline__ uint32_t smem_u32(const void* p){
    uint32_t a;
    asm("{ .reg .u64 t; cvta.to.shared.u64 t, %1; cvt.u32.u64 %0, t; }" : "=r"(a) : "l"(p));
    return a;
}
__device__ __forceinline__ uint32_t swz128(uint32_t off){ return off ^ ((off >> 3) & 0x70); }
__device__ __forceinline__ uint32_t bmul2(uint32_t a, uint32_t b){
    uint32_t d;
    asm("mul.rn.bf16x2 %0, %1, %2;" : "=r"(d) : "r"(a), "r"(b));
    return d;
}

// ---- warp-level bf16 tensor core ops (baseline PTX; works on .target sm_100) ----
__device__ __forceinline__ void ldm_x4(uint32_t* r, uint32_t addr){
    asm volatile("ldmatrix.sync.aligned.m8n8.x4.shared.b16 {%0,%1,%2,%3}, [%4];"
        : "=r"(r[0]), "=r"(r[1]), "=r"(r[2]), "=r"(r[3]) : "r"(addr));
}
__device__ __forceinline__ void ldm_x2(uint32_t* r, uint32_t addr){
    asm volatile("ldmatrix.sync.aligned.m8n8.x2.shared.b16 {%0,%1}, [%2];"
        : "=r"(r[0]), "=r"(r[1]) : "r"(addr));
}
__device__ __forceinline__ void mma16816(float* c, const uint32_t* a, const uint32_t* b){
    asm volatile("mma.sync.aligned.m16n8k16.row.col.f32.bf16.bf16.f32 "
        "{%0,%1,%2,%3}, {%4,%5,%6,%7}, {%8,%9}, {%0,%1,%2,%3};"
        : "+f"(c[0]), "+f"(c[1]), "+f"(c[2]), "+f"(c[3])
        : "r"(a[0]), "r"(a[1]), "r"(a[2]), "r"(a[3]), "r"(b[0]), "r"(b[1]));
}

// ---------------- K1b: ev (+ bf16 copy) ----------------
__global__ __launch_bounds__(64) void k1b_ev(const float* __restrict__ ein,
                                             const float* __restrict__ we,
                                             const float* __restrict__ be){
    __shared__ float e_s[H];
    const int c = blockIdx.x, tid = threadIdx.x;
    for (int i = tid; i < H; i += 64) e_s[i] = ein[(size_t)c*H + i];
    __syncthreads();
    float acc = 0.f;
#pragma unroll 1
    for (int h = 0; h < H; h += 4){
        float4 ev4 = *reinterpret_cast<const float4*>(&e_s[h]);
        acc = fmaf(ev4.x, we[(h+0)*D + tid], acc);
        acc = fmaf(ev4.y, we[(h+1)*D + tid], acc);
        acc = fmaf(ev4.z, we[(h+2)*D + tid], acc);
        acc = fmaf(ev4.w, we[(h+3)*D + tid], acc);
    }
    acc += be[tid];
    g_ev[c*D + tid]  = acc;
    g_evb[c*D + tid] = __float2bfloat16(acc);
}

// ---------------- K1: dense + RoPE -> qw,kw (fp32) + Qb,Kb (bf16) ----------------
#define K1_M 8
__global__ __launch_bounds__(128) void k1_qk(const float* __restrict__ inp,
                                             const float* __restrict__ wd,
                                             const float* __restrict__ bd){
    __shared__ float in_s[K1_M][H];
    __shared__ float seq_s[K1_M][128];
    const int b = blockIdx.y, m0 = blockIdx.x * K1_M, tid = threadIdx.x;

    const float* src = inp + ((size_t)b*NS + m0) * H;
    for (int i = tid; i < K1_M*H; i += 128) in_s[i/H][i%H] = src[i];
    __syncthreads();

    const int col = tid;
    float acc[K1_M];
#pragma unroll
    for (int mi = 0; mi < K1_M; mi++) acc[mi] = 0.f;
#pragma unroll 1
    for (int h = 0; h < H; h += 4){
        float w0 = wd[(h+0)*128 + col];
        float w1 = wd[(h+1)*128 + col];
        float w2 = wd[(h+2)*128 + col];
        float w3 = wd[(h+3)*128 + col];
#pragma unroll
        for (int mi = 0; mi < K1_M; mi++){
            float4 iv = *reinterpret_cast<const float4*>(&in_s[mi][h]);
            acc[mi] = fmaf(iv.x, w0, acc[mi]);
            acc[mi] = fmaf(iv.y, w1, acc[mi]);
            acc[mi] = fmaf(iv.z, w2, acc[mi]);
            acc[mi] = fmaf(iv.w, w3, acc[mi]);
        }
    }
    const float bb = bd[col];
#pragma unroll
    for (int mi = 0; mi < K1_M; mi++) seq_s[mi][col] = acc[mi] + bb;
    __syncthreads();

    for (int t = tid; t < K1_M*64; t += 128){
        int mi = t >> 6, p = t & 63;
        int which = p >> 5, j = p & 31;
        int m = m0 + mi;
        float divf = (float)exp((double)j * -0.28782313662425574);
        float ang  = (float)m * divf;
        double ad  = (double)ang;
        float cv = (float)cos(ad), sv = (float)sin(ad);
        int base = which*64 + 2*j;
        float x0 = seq_s[mi][base], x1 = seq_s[mi][base+1];
        float r0 = x0*cv - x1*sv;
        float r1 = x1*cv + x0*sv;
        size_t o = ((size_t)b*NS + m) * D + 2*j;
        if (which){
            g_kw[o] = r0; g_kw[o+1] = r1;
            g_Kb[o] = __float2bfloat16(r0); g_Kb[o+1] = __float2bfloat16(r1);
        } else {
            g_qw[o] = r0; g_qw[o+1] = r1;
            g_Qb[o] = __float2bfloat16(r0); g_Qb[o+1] = __float2bfloat16(r1);
        }
    }
}

// ---------------- K_sum2: column sums + chanMax init ----------------
__global__ __launch_bounds__(512) void k_sum2(){
    __shared__ float red[8][64];
    const int which = blockIdx.x, b = blockIdx.y;
    const int tid = threadIdx.x, d = tid & 63, part = tid >> 6;
    if (which == 0 && b == 0 && tid < B*C) g_chanMaxKey[tid] = 0u;
    const float* src = (which ? g_kw : g_qw) + (size_t)b*NS*D;
    float s = 0.f;
#pragma unroll 8
    for (int m = part; m < NS; m += 8) s += src[m*64 + d];
    red[part][d] = s;
    __syncthreads();
    if (tid < 64){
        float t = 0.f;
#pragma unroll
        for (int p = 0; p < 8; p++) t += red[p][tid];
        (which ? g_Ks : g_Qs)[b*64 + tid] = t;
    }
}

// ================= GEMM tile helpers: A = q (128x64), B = ev_c∘k (128x64) =================
__device__ __forceinline__ void load_tiles_qk(char* smem, int b, int c, int m0, int n0, int tid){
    const uint4* pQ = reinterpret_cast<const uint4*>(g_Qb);
    const uint4* pK = reinterpret_cast<const uint4*>(g_Kb);
    const size_t qbase = ((size_t)b*NS + m0) * 8;
    const size_t kbase = ((size_t)b*NS + n0) * 8;
    const int c16 = tid & 7;
    const uint4 ev4 = *reinterpret_cast<const uint4*>(g_evb + c*64 + c16*8);
#pragma unroll
    for (int it = 0; it < 4; it++){
        int i = it*256 + tid;
        int row = i >> 3;
        uint32_t so = swz128(row*128 + c16*16);
        *reinterpret_cast<uint4*>(smem + so) = pQ[qbase + (size_t)row*8 + c16];
        uint4 kv = pK[kbase + (size_t)row*8 + c16];
        kv.x = bmul2(kv.x, ev4.x); kv.y = bmul2(kv.y, ev4.y);
        kv.z = bmul2(kv.z, ev4.z); kv.w = bmul2(kv.w, ev4.w);
        *reinterpret_cast<uint4*>(smem + 16384 + so) = kv;
    }
}
__device__ __forceinline__ void mainloop_128(uint32_t sbA, uint32_t sbB, int warp_m, int warp_n,
                                             int lane, float acc[4][4][4]){
#pragma unroll
    for (int kt = 0; kt < 4; kt++){
        uint32_t af[4][4], bf[4][2];
#pragma unroll
        for (int i = 0; i < 4; i++){
            int row = warp_m*64 + i*16 + (lane & 15);
            ldm_x4(af[i], sbA + swz128(row*128 + kt*32 + (lane >> 4)*16));
        }
#pragma unroll
        for (int j = 0; j < 4; j++){
            int row = warp_n*32 + j*8 + (lane & 7);
            ldm_x2(bf[j], sbB + swz128(row*128 + kt*32 + ((lane >> 3) & 1)*16));
        }
#pragma unroll
        for (int i = 0; i < 4; i++)
#pragma unroll
            for (int j = 0; j < 4; j++)
                mma16816(acc[i][j], af[i], bf[j]);
    }
}

// ---------------- KP1: per-channel max (recompute) ----------------
__global__ __launch_bounds__(256) void kp1_chanmax(){
    __shared__ __align__(1024) char smem[32768];
    __shared__ float red_s[8];
    const uint32_t sbA = smem_u32(smem), sbB = sbA + 16384;
    const int tid = threadIdx.x, wid = tid >> 5, lane = tid & 31;
    const int warp_m = wid >> 2, warp_n = wid & 3;
    const int b = blockIdx.z, rt = blockIdx.y, n0 = blockIdx.x * 128;
    const int c = rt >> 2, m0 = (rt & 3) * 128;

    load_tiles_qk(smem, b, c, m0, n0, tid);
    __syncthreads();

    float acc[4][4][4];
#pragma unroll
    for (int i = 0; i < 4; i++)
#pragma unroll
        for (int j = 0; j < 4; j++)
#pragma unroll
            for (int r = 0; r < 4; r++) acc[i][j][r] = 0.f;
    mainloop_128(sbA, sbB, warp_m, warp_n, lane, acc);

    float mx = -3.402823466e38f;
#pragma unroll
    for (int i = 0; i < 4; i++)
#pragma unroll
        for (int j = 0; j < 4; j++)
#pragma unroll
            for (int r = 0; r < 4; r++) mx = fmaxf(mx, acc[i][j][r]);
#pragma unroll
    for (int off = 16; off > 0; off >>= 1)
        mx = fmaxf(mx, __shfl_xor_sync(0xffffffffu, mx, off));
    if (lane == 0) red_s[wid] = mx;
    __syncthreads();
    if (tid == 0){
        float m2 = red_s[0];
#pragma unroll
        for (int w = 1; w < 8; w++) m2 = fmaxf(m2, red_s[w]);
        atomicMax(&g_chanMaxKey[b*C + c], fkey(m2));
    }
}

// ---------------- K3: scale + evS (fp32 analytic avg; writes bf16 evS) ----------------
__global__ __launch_bounds__(128) void k3_scale(const float* __restrict__ w1, const float* __restrict__ b1,
                                                const float* __restrict__ w2, const float* __restrict__ b2){
    __shared__ float avg_s[C], mx_s[C], hid_s[12], sc_s[C];
    const int tid = threadIdx.x;
    for (int b = 0; b < B; b++){
        if (tid < C){
            float s = 0.f;
            for (int d = 0; d < D; d++)
                s = fmaf(g_ev[tid*D + d], g_Qs[b*D + d]*g_Ks[b*D + d], s);
            avg_s[tid] = s * (1.f/262144.f);
            mx_s[tid]  = fkeyinv(g_chanMaxKey[b*C + tid]);
        }
        __syncthreads();
        if (tid < 12){
            int which = tid / 6, j = tid % 6;
            const float* v = which ? mx_s : avg_s;
            float h = b1[j];
            for (int c2 = 0; c2 < C; c2++) h = fmaf(v[c2], w1[c2*CH_HID + j], h);
            hid_s[tid] = fmaxf(h, 0.f);
        }
        __syncthreads();
        if (tid < C){
            float z = 2.f * b2[tid];
            for (int j = 0; j < CH_HID; j++)
                z = fmaf(hid_s[j] + hid_s[6+j], w2[j*C + tid], z);
            float sc = 1.f / (1.f + expf(-z));
            g_scale[b*C + tid] = sc;
            sc_s[tid] = sc;
        }
        __syncthreads();
        if (tid < D){
            float s = 0.f;
            for (int c2 = 0; c2 < C; c2++)
                s = fmaf(sc_s[c2], g_ev[c2*D + tid], s);
            g_evSb[b*D + tid] = __float2bfloat16(s);
        }
        __syncthreads();
    }
}

// ---------------- KP2: register-resident channel loop -> comp max + mean ----------------
// tile m=64 x n=64; 256 thr (8 warps: 4m x 2n, warp tile 16x32). A/B frags loaded once;
// per channel: scale B frags by ev pairs (bf16x2) in registers, mma, update max.
// Mean = extra iteration with ev = evS (exact factorization), /108.
__global__ __launch_bounds__(256) void kp2_comp(){
    __shared__ __align__(1024) char smQ[8192];
    __shared__ __align__(1024) char smK[8192];
    __shared__ __nv_bfloat16 s_evb[C*D];       // 13.8 KB
    __shared__ __nv_bfloat16 s_evS[D];
    __shared__ float sc_s[C];
    const uint32_t sQ = smem_u32(smQ), sK = smem_u32(smK);
    const uint32_t sEV = smem_u32(s_evb);
    const int tid = threadIdx.x, wid = tid >> 5, lane = tid & 31;
    const int warp_m = wid >> 1, warp_n = wid & 1;
    const int b = blockIdx.z, m0 = blockIdx.y * 64, n0 = blockIdx.x * 64;

    if (tid < C) sc_s[tid] = g_scale[b*C + tid];
    if (tid < D) s_evS[tid] = g_evSb[b*D + tid];
    for (int i = tid; i < C*D/8; i += 256)
        reinterpret_cast<uint4*>(s_evb)[i] = reinterpret_cast<const uint4*>(g_evb)[i];
    {
        const uint4* pQ = reinterpret_cast<const uint4*>(g_Qb);
        const uint4* pK = reinterpret_cast<const uint4*>(g_Kb);
        const size_t qbase = ((size_t)b*NS + m0) * 8;
        const size_t kbase = ((size_t)b*NS + n0) * 8;
#pragma unroll
        for (int it = 0; it < 2; it++){
            int i = it*256 + tid;              // 512 uint4 each
            int row = i >> 3, c16 = i & 7;
            uint32_t so = swz128(row*128 + c16*16);
            *reinterpret_cast<uint4*>(smQ + so) = pQ[qbase + (size_t)row*8 + c16];
            *reinterpret_cast<uint4*>(smK + so) = pK[kbase + (size_t)row*8 + c16];
        }
    }
    __syncthreads();

    // A frags (fixed): 16 rows per warp
    uint32_t af[4][4];
#pragma unroll
    for (int kt = 0; kt < 4; kt++){
        int row = warp_m*16 + (lane & 15);
        ldm_x4(af[kt], sQ + swz128(row*128 + kt*32 + (lane >> 4)*16));
    }
    // base B frags (fixed): k
    uint32_t bf[4][4][2];
#pragma unroll
    for (int kt = 0; kt < 4; kt++)
#pragma unroll
        for (int j = 0; j < 4; j++){
            int row = warp_n*32 + j*8 + (lane & 7);
            ldm_x2(bf[kt][j], sK + swz128(row*128 + kt*32 + ((lane >> 3) & 1)*16));
        }

    // per-thread ev byte offsets: d = kt*16 + reg*8 + (lane&3)*2
    const int dlo = (lane & 3)*2;

    float mx[4][4], mean[4][4];
#pragma unroll
    for (int j = 0; j < 4; j++)
#pragma unroll
        for (int r = 0; r < 4; r++){ mx[j][r] = -3.402823466e38f; mean[j][r] = 0.f; }

#pragma unroll 1
    for (int c = 0; c < C; c++){
        uint32_t ev[4][2];
#pragma unroll
        for (int kt = 0; kt < 4; kt++)
#pragma unroll
            for (int reg = 0; reg < 2; reg++){
                uint32_t addr = sEV + (c*64 + kt*16 + reg*8 + dlo)*2;
                asm volatile("ld.shared.b32 %0, [%1];" : "=r"(ev[kt][reg]) : "r"(addr));
            }
        float acc[4][4];
#pragma unroll
        for (int j = 0; j < 4; j++)
#pragma unroll
            for (int r = 0; r < 4; r++) acc[j][r] = 0.f;
#pragma unroll
        for (int kt = 0; kt < 4; kt++)
#pragma unroll
            for (int j = 0; j < 4; j++){
                uint32_t sb[2];
                sb[0] = bmul2(bf[kt][j][0], ev[kt][0]);
                sb[1] = bmul2(bf[kt][j][1], ev[kt][1]);
                mma16816(acc[j], af[kt], sb);
            }
        const float sc = sc_s[c];
#pragma unroll
        for (int j = 0; j < 4; j++)
#pragma unroll
            for (int r = 0; r < 4; r++)
                mx[j][r] = fmaxf(mx[j][r], acc[j][r] * sc);
    }
    // mean via evS pseudo-channel
    {
        uint32_t ev[4][2];
        const uint32_t sES = smem_u32(s_evS);
#pragma unroll
        for (int kt = 0; kt < 4; kt++)
#pragma unroll
            for (int reg = 0; reg < 2; reg++){
                uint32_t addr = sES + (kt*16 + reg*8 + dlo)*2;
                asm volatile("ld.shared.b32 %0, [%1];" : "=r"(ev[kt][reg]) : "r"(addr));
            }
        float acc[4][4];
#pragma unroll
        for (int j = 0; j < 4; j++)
#pragma unroll
            for (int r = 0; r < 4; r++) acc[j][r] = 0.f;
#pragma unroll
        for (int kt = 0; kt < 4; kt++)
#pragma unroll
            for (int j = 0; j < 4; j++){
                uint32_t sb[2];
                sb[0] = bmul2(bf[kt][j][0], ev[kt][0]);
                sb[1] = bmul2(bf[kt][j][1], ev[kt][1]);
                mma16816(acc[j], af[kt], sb);
            }
#pragma unroll
        for (int j = 0; j < 4; j++)
#pragma unroll
            for (int r = 0; r < 4; r++) mean[j][r] = acc[j][r] * (1.f/108.f);
    }

    // write comp tiles
#pragma unroll
    for (int j = 0; j < 4; j++){
        int gm0 = m0 + warp_m*16 + (lane >> 2);
        int gn  = n0 + warp_n*32 + j*8 + (lane & 3)*2;
        size_t p0 = ((size_t)(b*NS + gm0))*NS + gn;
        size_t p1 = ((size_t)(b*NS + gm0 + 8))*NS + gn;
        *reinterpret_cast<float2*>(&g_compMax[p0])  = make_float2(mx[j][0], mx[j][1]);
        *reinterpret_cast<float2*>(&g_compMax[p1])  = make_float2(mx[j][2], mx[j][3]);
        *reinterpret_cast<float2*>(&g_compMean[p0]) = make_float2(mean[j][0], mean[j][1]);
        *reinterpret_cast<float2*>(&g_compMean[p1]) = make_float2(mean[j][2], mean[j][3]);
    }
}

// ---------------- K5: 7x7 conv + sigmoid ----------------
#define CT 16
__global__ __launch_bounds__(256) void k5_conv(const float* __restrict__ cw){
    __shared__ float smax[CT+6][CT+6];
    __shared__ float smean[CT+6][CT+6];
    __shared__ float w_s[98];
    const int b = blockIdx.z, m0 = blockIdx.y*CT, n0 = blockIdx.x*CT, tid = threadIdx.x;
    if (tid < 98) w_s[tid] = cw[tid];
    for (int i = tid; i < (CT+6)*(CT+6); i += 256){
        int r = i / (CT+6), cc = i % (CT+6);
        int gm = m0 + r - 3, gn = n0 + cc - 3;
        float a = 0.f, mn = 0.f;
        if (gm >= 0 && gm < NS && gn >= 0 && gn < NS){
            size_t gi = (size_t)(b*NS + gm)*NS + gn;
            a  = g_compMax[gi];
            mn = g_compMean[gi];
        }
        smax[r][cc] = a; smean[r][cc] = mn;
    }
    __syncthreads();
    const int ty = tid / CT, tx = tid % CT;
    float acc = 0.f;
#pragma unroll
    for (int kh = 0; kh < 7; kh++)
#pragma unroll
        for (int kw = 0; kw < 7; kw++){
            acc = fmaf(smax[ty+kh][tx+kw],  w_s[kh*7 + kw],      acc);
            acc = fmaf(smean[ty+kh][tx+kw], w_s[49 + kh*7 + kw], acc);
        }
    acc *= 0.9999950000374997f;
    g_sig[(size_t)(b*NS + m0 + ty)*NS + n0 + tx] = 1.f / (1.f + expf(-acc));
}

// ---------------- KP3: recompute -> fused final epilogue -> out ----------------
__global__ __launch_bounds__(256) void kp3_final(float* __restrict__ out, const int* __restrict__ mask){
    __shared__ __align__(1024) char smem[32768];
    __shared__ int mrow_s[128], mcol_s[128];
    const uint32_t sbA = smem_u32(smem), sbB = sbA + 16384;
    const int tid = threadIdx.x, wid = tid >> 5, lane = tid & 31;
    const int warp_m = wid >> 2, warp_n = wid & 3;
    const int b = blockIdx.z, rt = blockIdx.y, n0 = blockIdx.x * 128;
    const int c = rt >> 2, m0 = (rt & 3) * 128;

    load_tiles_qk(smem, b, c, m0, n0, tid);
    if (tid < 128){
        mrow_s[tid] = mask[b*NS + m0 + tid];
        mcol_s[tid] = mask[b*NS + n0 + tid];
    }
    __syncthreads();

    float acc[4][4][4];
#pragma unroll
    for (int i = 0; i < 4; i++)
#pragma unroll
        for (int j = 0; j < 4; j++)
#pragma unroll
            for (int r = 0; r < 4; r++) acc[i][j][r] = 0.f;
    mainloop_128(sbA, sbB, warp_m, warp_n, lane, acc);

    const float sc = g_scale[b*C + c];
    const size_t obase = ((size_t)(b*C + c)*NS + m0)*NS + n0;
    const float NEGINF = __int_as_float(0xff800000);
#pragma unroll
    for (int i = 0; i < 4; i++){
        int lrow0 = warp_m*64 + i*16 + (lane >> 2);
#pragma unroll
        for (int j = 0; j < 4; j++){
            int lcol = warp_n*32 + j*8 + (lane & 3)*2;
            int gn = n0 + lcol;
            int mc0 = mcol_s[lcol], mc1 = mcol_s[lcol+1];
#pragma unroll
            for (int h = 0; h < 2; h++){
                int lrow = lrow0 + h*8;
                int gm = m0 + lrow;
                float2 sg = *reinterpret_cast<const float2*>(&g_sig[((size_t)(b*NS + gm))*NS + gn]);
                int mr = mrow_s[lrow];
                float y0 = acc[i][j][2*h]   * fmaf(sc, sg.x, 1.f);
                float y1 = acc[i][j][2*h+1] * fmaf(sc, sg.y, 1.f);
                if (gm > gn)     y0 -= 1e12f;
                if (gm > gn + 1) y1 -= 1e12f;
                if (mr == 0 || mc0 == 0) y0 = NEGINF;
                if (mr == 0 || mc1 == 0) y1 = NEGINF;
                *reinterpret_cast<float2*>(&out[obase + (size_t)lrow*NS + lcol]) =
                    make_float2(y0 * 0.125f, y1 * 0.125f);
            }
        }
    }
}

// ---------------- launcher ----------------
extern "C" void kernel_launch(void* const* d_in, const int* in_sizes, int n_in,
                              void* d_out, int out_size){
    (void)in_sizes; (void)n_in; (void)out_size;
    const float* inputs       = (const float*)d_in[0];
    const float* event_inputs = (const float*)d_in[1];
    const int*   mask         = (const int*)  d_in[2];
    const float* w_dense      = (const float*)d_in[3];
    const float* b_dense      = (const float*)d_in[4];
    const float* w_event      = (const float*)d_in[5];
    const float* b_event      = (const float*)d_in[6];
    const float* mlp_w1       = (const float*)d_in[7];
    const float* mlp_b1       = (const float*)d_in[8];
    const float* mlp_w2       = (const float*)d_in[9];
    const float* mlp_b2       = (const float*)d_in[10];
    const float* conv_w       = (const float*)d_in[11];
    float* out = (float*)d_out;

    k1b_ev<<<108, 64>>>(event_inputs, w_event, b_event);
    k1_qk<<<dim3(64, 2), 128>>>(inputs, w_dense, b_dense);
    k_sum2<<<dim3(2, 2), 512>>>();
    kp1_chanmax<<<dim3(4, 432, 2), 256>>>();          // 4th launch -> profiled
    k3_scale<<<1, 128>>>(mlp_w1, mlp_b1, mlp_w2, mlp_b2);
    kp2_comp<<<dim3(8, 8, 2), 256>>>();
    k5_conv<<<dim3(32, 32, 2), 256>>>(conv_w);
    kp3_final<<<dim3(4, 432, 2), 256>>>(out, mask);
}

// round 12
// speedup vs baseline: 1.0949x; 1.0158x over previous
#include <cuda_runtime.h>
#include <cuda_bf16.h>
#include <cstdint>
#include <math.h>

#define B   2
#define NS  512
#define H   768
#define C   108
#define D   64
#define PIX (NS*NS)
#define CH_HID 6
#define NSPLIT 4
#define CSPL  27

// ---------------- device scratch ----------------
__device__ float          g_qw[B*NS*D];
__device__ float          g_kw[B*NS*D];
__device__ float          g_ev[C*D];
__device__ __nv_bfloat16  g_evb[C*D];        // bf16(ev)
__device__ __nv_bfloat16  g_evSb[B*D];       // bf16(sum_c scale_c*ev_c)
__device__ float          g_Qs[B*D];
__device__ float          g_Ks[B*D];
__device__ unsigned       g_chanMaxKey[B*C];
__device__ float          g_scale[B*C];
__device__ float          g_cmax[NSPLIT][B*PIX];   // per-split pixel max
__device__ float          g_compMean[B*PIX];
__device__ float          g_sig[B*PIX];
__device__ __nv_bfloat16  g_Qb[B*NS*D];      // bf16(q) 128KB
__device__ __nv_bfloat16  g_Kb[B*NS*D];      // bf16(k) 128KB

__device__ __forceinline__ unsigned fkey(float f){
    unsigned u = __float_as_uint(f);
    return (u & 0x80000000u) ? ~u : (u | 0x80000000u);
}
__device__ __forceinline__ float fkeyinv(unsigned k){
    return __uint_as_float((k & 0x80000000u) ? (k & 0x7fffffffu) : ~k);
}
__device__ __forceinline__ uint32_t smem_u32(const void* p){
    uint32_t a;
    asm("{ .reg .u64 t; cvta.to.shared.u64 t, %1; cvt.u32.u64 %0, t; }" : "=r"(a) : "l"(p));
    return a;
}
__device__ __forceinline__ uint32_t swz128(uint32_t off){ return off ^ ((off >> 3) & 0x70); }
__device__ __forceinline__ uint32_t bmul2(uint32_t a, uint32_t b){
    uint32_t d;
    asm("mul.rn.bf16x2 %0, %1, %2;" : "=r"(d) : "r"(a), "r"(b));
    return d;
}

// ---- warp-level bf16 tensor core ops ----
__device__ __forceinline__ void ldm_x4(uint32_t* r, uint32_t addr){
    asm volatile("ldmatrix.sync.aligned.m8n8.x4.shared.b16 {%0,%1,%2,%3}, [%4];"
        : "=r"(r[0]), "=r"(r[1]), "=r"(r[2]), "=r"(r[3]) : "r"(addr));
}
__device__ __forceinline__ void ldm_x2(uint32_t* r, uint32_t addr){
    asm volatile("ldmatrix.sync.aligned.m8n8.x2.shared.b16 {%0,%1}, [%2];"
        : "=r"(r[0]), "=r"(r[1]) : "r"(addr));
}
__device__ __forceinline__ void mma16816(float* c, const uint32_t* a, const uint32_t* b){
    asm volatile("mma.sync.aligned.m16n8k16.row.col.f32.bf16.bf16.f32 "
        "{%0,%1,%2,%3}, {%4,%5,%6,%7}, {%8,%9}, {%0,%1,%2,%3};"
        : "+f"(c[0]), "+f"(c[1]), "+f"(c[2]), "+f"(c[3])
        : "r"(a[0]), "r"(a[1]), "r"(a[2]), "r"(a[3]), "r"(b[0]), "r"(b[1]));
}

// ---------------- K1b: ev (+ bf16 copy) ----------------
__global__ __launch_bounds__(64) void k1b_ev(const float* __restrict__ ein,
                                             const float* __restrict__ we,
                                             const float* __restrict__ be){
    __shared__ float e_s[H];
    const int c = blockIdx.x, tid = threadIdx.x;
    for (int i = tid; i < H; i += 64) e_s[i] = ein[(size_t)c*H + i];
    __syncthreads();
    float acc = 0.f;
#pragma unroll 1
    for (int h = 0; h < H; h += 4){
        float4 ev4 = *reinterpret_cast<const float4*>(&e_s[h]);
        acc = fmaf(ev4.x, we[(h+0)*D + tid], acc);
        acc = fmaf(ev4.y, we[(h+1)*D + tid], acc);
        acc = fmaf(ev4.z, we[(h+2)*D + tid], acc);
        acc = fmaf(ev4.w, we[(h+3)*D + tid], acc);
    }
    acc += be[tid];
    g_ev[c*D + tid]  = acc;
    g_evb[c*D + tid] = __float2bfloat16(acc);
}

// ---------------- K1: dense + RoPE -> qw,kw (fp32) + Qb,Kb (bf16) ----------------
#define K1_M 8
__global__ __launch_bounds__(128) void k1_qk(const float* __restrict__ inp,
                                             const float* __restrict__ wd,
                                             const float* __restrict__ bd){
    __shared__ float in_s[K1_M][H];
    __shared__ float seq_s[K1_M][128];
    const int b = blockIdx.y, m0 = blockIdx.x * K1_M, tid = threadIdx.x;

    const float* src = inp + ((size_t)b*NS + m0) * H;
    for (int i = tid; i < K1_M*H; i += 128) in_s[i/H][i%H] = src[i];
    __syncthreads();

    const int col = tid;
    float acc[K1_M];
#pragma unroll
    for (int mi = 0; mi < K1_M; mi++) acc[mi] = 0.f;
#pragma unroll 1
    for (int h = 0; h < H; h += 4){
        float w0 = wd[(h+0)*128 + col];
        float w1 = wd[(h+1)*128 + col];
        float w2 = wd[(h+2)*128 + col];
        float w3 = wd[(h+3)*128 + col];
#pragma unroll
        for (int mi = 0; mi < K1_M; mi++){
            float4 iv = *reinterpret_cast<const float4*>(&in_s[mi][h]);
            acc[mi] = fmaf(iv.x, w0, acc[mi]);
            acc[mi] = fmaf(iv.y, w1, acc[mi]);
            acc[mi] = fmaf(iv.z, w2, acc[mi]);
            acc[mi] = fmaf(iv.w, w3, acc[mi]);
        }
    }
    const float bb = bd[col];
#pragma unroll
    for (int mi = 0; mi < K1_M; mi++) seq_s[mi][col] = acc[mi] + bb;
    __syncthreads();

    for (int t = tid; t < K1_M*64; t += 128){
        int mi = t >> 6, p = t & 63;
        int which = p >> 5, j = p & 31;
        int m = m0 + mi;
        float divf = (float)exp((double)j * -0.28782313662425574);
        float ang  = (float)m * divf;
        double ad  = (double)ang;
        float cv = (float)cos(ad), sv = (float)sin(ad);
        int base = which*64 + 2*j;
        float x0 = seq_s[mi][base], x1 = seq_s[mi][base+1];
        float r0 = x0*cv - x1*sv;
        float r1 = x1*cv + x0*sv;
        size_t o = ((size_t)b*NS + m) * D + 2*j;
        if (which){
            g_kw[o] = r0; g_kw[o+1] = r1;
            g_Kb[o] = __float2bfloat16(r0); g_Kb[o+1] = __float2bfloat16(r1);
        } else {
            g_qw[o] = r0; g_qw[o+1] = r1;
            g_Qb[o] = __float2bfloat16(r0); g_Qb[o+1] = __float2bfloat16(r1);
        }
    }
}

// ---------------- K_sum2: column sums + chanMax init ----------------
__global__ __launch_bounds__(512) void k_sum2(){
    __shared__ float red[8][64];
    const int which = blockIdx.x, b = blockIdx.y;
    const int tid = threadIdx.x, d = tid & 63, part = tid >> 6;
    if (which == 0 && b == 0 && tid < B*C) g_chanMaxKey[tid] = 0u;
    const float* src = (which ? g_kw : g_qw) + (size_t)b*NS*D;
    float s = 0.f;
#pragma unroll 8
    for (int m = part; m < NS; m += 8) s += src[m*64 + d];
    red[part][d] = s;
    __syncthreads();
    if (tid < 64){
        float t = 0.f;
#pragma unroll
        for (int p = 0; p < 8; p++) t += red[p][tid];
        (which ? g_Ks : g_Qs)[b*64 + tid] = t;
    }
}

// ================= GEMM tile helpers: A = q (128x64), B = ev_c∘k (128x64) =================
__device__ __forceinline__ void load_tiles_qk(char* smem, int b, int c, int m0, int n0, int tid){
    const uint4* pQ = reinterpret_cast<const uint4*>(g_Qb);
    const uint4* pK = reinterpret_cast<const uint4*>(g_Kb);
    const size_t qbase = ((size_t)b*NS + m0) * 8;
    const size_t kbase = ((size_t)b*NS + n0) * 8;
    const int c16 = tid & 7;
    const uint4 ev4 = *reinterpret_cast<const uint4*>(g_evb + c*64 + c16*8);
#pragma unroll
    for (int it = 0; it < 4; it++){
        int i = it*256 + tid;
        int row = i >> 3;
        uint32_t so = swz128(row*128 + c16*16);
        *reinterpret_cast<uint4*>(smem + so) = pQ[qbase + (size_t)row*8 + c16];
        uint4 kv = pK[kbase + (size_t)row*8 + c16];
        kv.x = bmul2(kv.x, ev4.x); kv.y = bmul2(kv.y, ev4.y);
        kv.z = bmul2(kv.z, ev4.z); kv.w = bmul2(kv.w, ev4.w);
        *reinterpret_cast<uint4*>(smem + 16384 + so) = kv;
    }
}
__device__ __forceinline__ void mainloop_128(uint32_t sbA, uint32_t sbB, int warp_m, int warp_n,
                                             int lane, float acc[4][4][4]){
#pragma unroll
    for (int kt = 0; kt < 4; kt++){
        uint32_t af[4][4], bf[4][2];
#pragma unroll
        for (int i = 0; i < 4; i++){
            int row = warp_m*64 + i*16 + (lane & 15);
            ldm_x4(af[i], sbA + swz128(row*128 + kt*32 + (lane >> 4)*16));
        }
#pragma unroll
        for (int j = 0; j < 4; j++){
            int row = warp_n*32 + j*8 + (lane & 7);
            ldm_x2(bf[j], sbB + swz128(row*128 + kt*32 + ((lane >> 3) & 1)*16));
        }
#pragma unroll
        for (int i = 0; i < 4; i++)
#pragma unroll
            for (int j = 0; j < 4; j++)
                mma16816(acc[i][j], af[i], bf[j]);
    }
}

// ---------------- KP1: per-channel max (recompute) ----------------
__global__ __launch_bounds__(256) void kp1_chanmax(){
    __shared__ __align__(1024) char smem[32768];
    __shared__ float red_s[8];
    const uint32_t sbA = smem_u32(smem), sbB = sbA + 16384;
    const int tid = threadIdx.x, wid = tid >> 5, lane = tid & 31;
    const int warp_m = wid >> 2, warp_n = wid & 3;
    const int b = blockIdx.z, rt = blockIdx.y, n0 = blockIdx.x * 128;
    const int c = rt >> 2, m0 = (rt & 3) * 128;

    load_tiles_qk(smem, b, c, m0, n0, tid);
    __syncthreads();

    float acc[4][4][4];
#pragma unroll
    for (int i = 0; i < 4; i++)
#pragma unroll
        for (int j = 0; j < 4; j++)
#pragma unroll
            for (int r = 0; r < 4; r++) acc[i][j][r] = 0.f;
    mainloop_128(sbA, sbB, warp_m, warp_n, lane, acc);

    float mx = -3.402823466e38f;
#pragma unroll
    for (int i = 0; i < 4; i++)
#pragma unroll
        for (int j = 0; j < 4; j++)
#pragma unroll
            for (int r = 0; r < 4; r++) mx = fmaxf(mx, acc[i][j][r]);
#pragma unroll
    for (int off = 16; off > 0; off >>= 1)
        mx = fmaxf(mx, __shfl_xor_sync(0xffffffffu, mx, off));
    if (lane == 0) red_s[wid] = mx;
    __syncthreads();
    if (tid == 0){
        float m2 = red_s[0];
#pragma unroll
        for (int w = 1; w < 8; w++) m2 = fmaxf(m2, red_s[w]);
        atomicMax(&g_chanMaxKey[b*C + c], fkey(m2));
    }
}

// ---------------- K3: scale + evS ----------------
__global__ __launch_bounds__(128) void k3_scale(const float* __restrict__ w1, const float* __restrict__ b1,
                                                const float* __restrict__ w2, const float* __restrict__ b2){
    __shared__ float avg_s[C], mx_s[C], hid_s[12], sc_s[C];
    const int tid = threadIdx.x;
    for (int b = 0; b < B; b++){
        if (tid < C){
            float s = 0.f;
            for (int d = 0; d < D; d++)
                s = fmaf(g_ev[tid*D + d], g_Qs[b*D + d]*g_Ks[b*D + d], s);
            avg_s[tid] = s * (1.f/262144.f);
            mx_s[tid]  = fkeyinv(g_chanMaxKey[b*C + tid]);
        }
        __syncthreads();
        if (tid < 12){
            int which = tid / 6, j = tid % 6;
            const float* v = which ? mx_s : avg_s;
            float h = b1[j];
            for (int c2 = 0; c2 < C; c2++) h = fmaf(v[c2], w1[c2*CH_HID + j], h);
            hid_s[tid] = fmaxf(h, 0.f);
        }
        __syncthreads();
        if (tid < C){
            float z = 2.f * b2[tid];
            for (int j = 0; j < CH_HID; j++)
                z = fmaf(hid_s[j] + hid_s[6+j], w2[j*C + tid], z);
            float sc = 1.f / (1.f + expf(-z));
            g_scale[b*C + tid] = sc;
            sc_s[tid] = sc;
        }
        __syncthreads();
        if (tid < D){
            float s = 0.f;
            for (int c2 = 0; c2 < C; c2++)
                s = fmaf(sc_s[c2], g_ev[c2*D + tid], s);
            g_evSb[b*D + tid] = __float2bfloat16(s);
        }
        __syncthreads();
    }
}

// ---------------- KP2: register-resident channel loop, 4-way channel split ----------------
// tile m=64 x n=64; 256 thr (8 warps: 4m x 2n, warp tile 16x32). Frags loaded once;
// per channel: scale B frags by ev pairs (bf16x2), mma, update max. Split 3 adds the
// evS pseudo-channel for the exact mean. 1024 blocks -> ~7/SM.
__global__ __launch_bounds__(256) void kp2_comp(){
    __shared__ __align__(1024) char smQ[8192];
    __shared__ __align__(1024) char smK[8192];
    __shared__ __nv_bfloat16 s_evb[CSPL*D];    // 3.4 KB slice
    __shared__ __nv_bfloat16 s_evS[D];
    __shared__ float sc_s[CSPL];
    const uint32_t sQ = smem_u32(smQ), sK = smem_u32(smK);
    const uint32_t sEV = smem_u32(s_evb);
    const int tid = threadIdx.x, wid = tid >> 5, lane = tid & 31;
    const int warp_m = wid >> 1, warp_n = wid & 1;
    const int z = blockIdx.z;
    const int b = z >> 2, split = z & 3;
    const int c0 = split * CSPL;
    const int m0 = blockIdx.y * 64, n0 = blockIdx.x * 64;

    if (tid < CSPL) sc_s[tid] = g_scale[b*C + c0 + tid];
    if (tid < D) s_evS[tid] = g_evSb[b*D + tid];
    for (int i = tid; i < CSPL*D/8; i += 256)
        reinterpret_cast<uint4*>(s_evb)[i] = reinterpret_cast<const uint4*>(g_evb + c0*D)[i];
    {
        const uint4* pQ = reinterpret_cast<const uint4*>(g_Qb);
        const uint4* pK = reinterpret_cast<const uint4*>(g_Kb);
        const size_t qbase = ((size_t)b*NS + m0) * 8;
        const size_t kbase = ((size_t)b*NS + n0) * 8;
#pragma unroll
        for (int it = 0; it < 2; it++){
            int i = it*256 + tid;
            int row = i >> 3, c16 = i & 7;
            uint32_t so = swz128(row*128 + c16*16);
            *reinterpret_cast<uint4*>(smQ + so) = pQ[qbase + (size_t)row*8 + c16];
            *reinterpret_cast<uint4*>(smK + so) = pK[kbase + (size_t)row*8 + c16];
        }
    }
    __syncthreads();

    uint32_t af[4][4];
#pragma unroll
    for (int kt = 0; kt < 4; kt++){
        int row = warp_m*16 + (lane & 15);
        ldm_x4(af[kt], sQ + swz128(row*128 + kt*32 + (lane >> 4)*16));
    }
    uint32_t bf[4][4][2];
#pragma unroll
    for (int kt = 0; kt < 4; kt++)
#pragma unroll
        for (int j = 0; j < 4; j++){
            int row = warp_n*32 + j*8 + (lane & 7);
            ldm_x2(bf[kt][j], sK + swz128(row*128 + kt*32 + ((lane >> 3) & 1)*16));
        }

    const int dlo = (lane & 3)*2;

    float mx[4][4];
#pragma unroll
    for (int j = 0; j < 4; j++)
#pragma unroll
        for (int r = 0; r < 4; r++) mx[j][r] = -3.402823466e38f;

#pragma unroll 1
    for (int c = 0; c < CSPL; c++){
        uint32_t ev[4][2];
#pragma unroll
        for (int kt = 0; kt < 4; kt++)
#pragma unroll
            for (int reg = 0; reg < 2; reg++){
                uint32_t addr = sEV + (c*64 + kt*16 + reg*8 + dlo)*2;
                asm volatile("ld.shared.b32 %0, [%1];" : "=r"(ev[kt][reg]) : "r"(addr));
            }
        float acc[4][4];
#pragma unroll
        for (int j = 0; j < 4; j++)
#pragma unroll
            for (int r = 0; r < 4; r++) acc[j][r] = 0.f;
#pragma unroll
        for (int kt = 0; kt < 4; kt++)
#pragma unroll
            for (int j = 0; j < 4; j++){
                uint32_t sb[2];
                sb[0] = bmul2(bf[kt][j][0], ev[kt][0]);
                sb[1] = bmul2(bf[kt][j][1], ev[kt][1]);
                mma16816(acc[j], af[kt], sb);
            }
        const float sc = sc_s[c];
#pragma unroll
        for (int j = 0; j < 4; j++)
#pragma unroll
            for (int r = 0; r < 4; r++)
                mx[j][r] = fmaxf(mx[j][r], acc[j][r] * sc);
    }

    float* outb = g_cmax[split];
#pragma unroll
    for (int j = 0; j < 4; j++){
        int gm0 = m0 + warp_m*16 + (lane >> 2);
        int gn  = n0 + warp_n*32 + j*8 + (lane & 3)*2;
        size_t p0 = ((size_t)(b*NS + gm0))*NS + gn;
        size_t p1 = ((size_t)(b*NS + gm0 + 8))*NS + gn;
        *reinterpret_cast<float2*>(&outb[p0]) = make_float2(mx[j][0], mx[j][1]);
        *reinterpret_cast<float2*>(&outb[p1]) = make_float2(mx[j][2], mx[j][3]);
    }

    if (split == 3){
        // mean via evS pseudo-channel (exact factorization)
        uint32_t ev[4][2];
        const uint32_t sES = smem_u32(s_evS);
#pragma unroll
        for (int kt = 0; kt < 4; kt++)
#pragma unroll
            for (int reg = 0; reg < 2; reg++){
                uint32_t addr = sES + (kt*16 + reg*8 + dlo)*2;
                asm volatile("ld.shared.b32 %0, [%1];" : "=r"(ev[kt][reg]) : "r"(addr));
            }
        float acc[4][4];
#pragma unroll
        for (int j = 0; j < 4; j++)
#pragma unroll
            for (int r = 0; r < 4; r++) acc[j][r] = 0.f;
#pragma unroll
        for (int kt = 0; kt < 4; kt++)
#pragma unroll
            for (int j = 0; j < 4; j++){
                uint32_t sb[2];
                sb[0] = bmul2(bf[kt][j][0], ev[kt][0]);
                sb[1] = bmul2(bf[kt][j][1], ev[kt][1]);
                mma16816(acc[j], af[kt], sb);
            }
#pragma unroll
        for (int j = 0; j < 4; j++){
            int gm0 = m0 + warp_m*16 + (lane >> 2);
            int gn  = n0 + warp_n*32 + j*8 + (lane & 3)*2;
            size_t p0 = ((size_t)(b*NS + gm0))*NS + gn;
            size_t p1 = ((size_t)(b*NS + gm0 + 8))*NS + gn;
            *reinterpret_cast<float2*>(&g_compMean[p0]) = make_float2(acc[j][0]*(1.f/108.f), acc[j][1]*(1.f/108.f));
            *reinterpret_cast<float2*>(&g_compMean[p1]) = make_float2(acc[j][2]*(1.f/108.f), acc[j][3]*(1.f/108.f));
        }
    }
}

// ---------------- K5: 7x7 conv + sigmoid (combines 4 max splits) ----------------
#define CT 16
__global__ __launch_bounds__(256) void k5_conv(const float* __restrict__ cw){
    __shared__ float smax[CT+6][CT+6];
    __shared__ float smean[CT+6][CT+6];
    __shared__ float w_s[98];
    const int b = blockIdx.z, m0 = blockIdx.y*CT, n0 = blockIdx.x*CT, tid = threadIdx.x;
    if (tid < 98) w_s[tid] = cw[tid];
    for (int i = tid; i < (CT+6)*(CT+6); i += 256){
        int r = i / (CT+6), cc = i % (CT+6);
        int gm = m0 + r - 3, gn = n0 + cc - 3;
        float a = 0.f, mn = 0.f;
        if (gm >= 0 && gm < NS && gn >= 0 && gn < NS){
            size_t gi = (size_t)(b*NS + gm)*NS + gn;
            a = fmaxf(fmaxf(g_cmax[0][gi], g_cmax[1][gi]),
                      fmaxf(g_cmax[2][gi], g_cmax[3][gi]));
            mn = g_compMean[gi];
        }
        smax[r][cc] = a; smean[r][cc] = mn;
    }
    __syncthreads();
    const int ty = tid / CT, tx = tid % CT;
    float acc = 0.f;
#pragma unroll
    for (int kh = 0; kh < 7; kh++)
#pragma unroll
        for (int kw = 0; kw < 7; kw++){
            acc = fmaf(smax[ty+kh][tx+kw],  w_s[kh*7 + kw],      acc);
            acc = fmaf(smean[ty+kh][tx+kw], w_s[49 + kh*7 + kw], acc);
        }
    acc *= 0.9999950000374997f;
    g_sig[(size_t)(b*NS + m0 + ty)*NS + n0 + tx] = 1.f / (1.f + expf(-acc));
}

// ---------------- KP3: recompute -> fused final epilogue -> out ----------------
__global__ __launch_bounds__(256) void kp3_final(float* __restrict__ out, const int* __restrict__ mask){
    __shared__ __align__(1024) char smem[32768];
    __shared__ int mrow_s[128], mcol_s[128];
    const uint32_t sbA = smem_u32(smem), sbB = sbA + 16384;
    const int tid = threadIdx.x, wid = tid >> 5, lane = tid & 31;
    const int warp_m = wid >> 2, warp_n = wid & 3;
    const int b = blockIdx.z, rt = blockIdx.y, n0 = blockIdx.x * 128;
    const int c = rt >> 2, m0 = (rt & 3) * 128;

    load_tiles_qk(smem, b, c, m0, n0, tid);
    if (tid < 128){
        mrow_s[tid] = mask[b*NS + m0 + tid];
        mcol_s[tid] = mask[b*NS + n0 + tid];
    }
    __syncthreads();

    float acc[4][4][4];
#pragma unroll
    for (int i = 0; i < 4; i++)
#pragma unroll
        for (int j = 0; j < 4; j++)
#pragma unroll
            for (int r = 0; r < 4; r++) acc[i][j][r] = 0.f;
    mainloop_128(sbA, sbB, warp_m, warp_n, lane, acc);

    const float sc = g_scale[b*C + c];
    const size_t obase = ((size_t)(b*C + c)*NS + m0)*NS + n0;
    const float NEGINF = __int_as_float(0xff800000);
#pragma unroll
    for (int i = 0; i < 4; i++){
        int lrow0 = warp_m*64 + i*16 + (lane >> 2);
#pragma unroll
        for (int j = 0; j < 4; j++){
            int lcol = warp_n*32 + j*8 + (lane & 3)*2;
            int gn = n0 + lcol;
            int mc0 = mcol_s[lcol], mc1 = mcol_s[lcol+1];
#pragma unroll
            for (int h = 0; h < 2; h++){
                int lrow = lrow0 + h*8;
                int gm = m0 + lrow;
                float2 sg = *reinterpret_cast<const float2*>(&g_sig[((size_t)(b*NS + gm))*NS + gn]);
                int mr = mrow_s[lrow];
                float y0 = acc[i][j][2*h]   * fmaf(sc, sg.x, 1.f);
                float y1 = acc[i][j][2*h+1] * fmaf(sc, sg.y, 1.f);
                if (gm > gn)     y0 -= 1e12f;
                if (gm > gn + 1) y1 -= 1e12f;
                if (mr == 0 || mc0 == 0) y0 = NEGINF;
                if (mr == 0 || mc1 == 0) y1 = NEGINF;
                *reinterpret_cast<float2*>(&out[obase + (size_t)lrow*NS + lcol]) =
                    make_float2(y0 * 0.125f, y1 * 0.125f);
            }
        }
    }
}

// ---------------- launcher ----------------
extern "C" void kernel_launch(void* const* d_in, const int* in_sizes, int n_in,
                              void* d_out, int out_size){
    (void)in_sizes; (void)n_in; (void)out_size;
    const float* inputs       = (const float*)d_in[0];
    const float* event_inputs = (const float*)d_in[1];
    const int*   mask         = (const int*)  d_in[2];
    const float* w_dense      = (const float*)d_in[3];
    const float* b_dense      = (const float*)d_in[4];
    const float* w_event      = (const float*)d_in[5];
    const float* b_event      = (const float*)d_in[6];
    const float* mlp_w1       = (const float*)d_in[7];
    const float* mlp_b1       = (const float*)d_in[8];
    const float* mlp_w2       = (const float*)d_in[9];
    const float* mlp_b2       = (const float*)d_in[10];
    const float* conv_w       = (const float*)d_in[11];
    float* out = (float*)d_out;

    k1b_ev<<<108, 64>>>(event_inputs, w_event, b_event);
    k1_qk<<<dim3(64, 2), 128>>>(inputs, w_dense, b_dense);
    k_sum2<<<dim3(2, 2), 512>>>();
    kp1_chanmax<<<dim3(4, 432, 2), 256>>>();
    k3_scale<<<1, 128>>>(mlp_w1, mlp_b1, mlp_w2, mlp_b2);
    kp2_comp<<<dim3(8, 8, 2*NSPLIT), 256>>>();
    k5_conv<<<dim3(32, 32, 2), 256>>>(conv_w);
    kp3_final<<<dim3(4, 432, 2), 256>>>(out, mask);
}

// round 13
// speedup vs baseline: 1.1007x; 1.0053x over previous
#include <cuda_runtime.h>
#include <cuda_bf16.h>
#include <cstdint>
#include <math.h>

#define B   2
#define NS  512
#define H   768
#define C   108
#define D   64
#define PIX (NS*NS)
#define CH_HID 6
#define NSPLIT 4
#define CSPL  27

// ---------------- device scratch ----------------
__device__ float          g_qw[B*NS*D];
__device__ float          g_kw[B*NS*D];
__device__ float          g_ev[C*D];
__device__ __nv_bfloat16  g_evb[C*D];        // bf16(ev)
__device__ __nv_bfloat16  g_evSb[B*D];       // bf16(sum_c scale_c*ev_c)
__device__ float          g_Qs[B*D];
__device__ float          g_Ks[B*D];
__device__ unsigned       g_chanMaxKey[B*C];
__device__ float          g_scale[B*C];
__device__ float          g_cmax[NSPLIT][B*PIX];   // per-split pixel max
__device__ float          g_compMean[B*PIX];
__device__ float          g_sig[B*PIX];
__device__ __nv_bfloat16  g_Qb[B*NS*D];      // bf16(q) 128KB
__device__ __nv_bfloat16  g_Kb[B*NS*D];      // bf16(k) 128KB

__device__ __forceinline__ unsigned fkey(float f){
    unsigned u = __float_as_uint(f);
    return (u & 0x80000000u) ? ~u : (u | 0x80000000u);
}
__device__ __forceinline__ float fkeyinv(unsigned k){
    return __uint_as_float((k & 0x80000000u) ? (k & 0x7fffffffu) : ~k);
}
__device__ __forceinline__ uint32_t smem_u32(const void* p){
    uint32_t a;
    asm("{ .reg .u64 t; cvta.to.shared.u64 t, %1; cvt.u32.u64 %0, t; }" : "=r"(a) : "l"(p));
    return a;
}
__device__ __forceinline__ uint32_t swz128(uint32_t off){ return off ^ ((off >> 3) & 0x70); }
__device__ __forceinline__ uint32_t bmul2(uint32_t a, uint32_t b){
    uint32_t d;
    asm("mul.rn.bf16x2 %0, %1, %2;" : "=r"(d) : "r"(a), "r"(b));
    return d;
}

// ---- warp-level bf16 tensor core ops ----
__device__ __forceinline__ void ldm_x4(uint32_t* r, uint32_t addr){
    asm volatile("ldmatrix.sync.aligned.m8n8.x4.shared.b16 {%0,%1,%2,%3}, [%4];"
        : "=r"(r[0]), "=r"(r[1]), "=r"(r[2]), "=r"(r[3]) : "r"(addr));
}
__device__ __forceinline__ void ldm_x2(uint32_t* r, uint32_t addr){
    asm volatile("ldmatrix.sync.aligned.m8n8.x2.shared.b16 {%0,%1}, [%2];"
        : "=r"(r[0]), "=r"(r[1]) : "r"(addr));
}
__device__ __forceinline__ void mma16816(float* c, const uint32_t* a, const uint32_t* b){
    asm volatile("mma.sync.aligned.m16n8k16.row.col.f32.bf16.bf16.f32 "
        "{%0,%1,%2,%3}, {%4,%5,%6,%7}, {%8,%9}, {%0,%1,%2,%3};"
        : "+f"(c[0]), "+f"(c[1]), "+f"(c[2]), "+f"(c[3])
        : "r"(a[0]), "r"(a[1]), "r"(a[2]), "r"(a[3]), "r"(b[0]), "r"(b[1]));
}

// ---------------- K1b: ev (+ bf16 copy) ----------------
__global__ __launch_bounds__(64) void k1b_ev(const float* __restrict__ ein,
                                             const float* __restrict__ we,
                                             const float* __restrict__ be){
    __shared__ float e_s[H];
    const int c = blockIdx.x, tid = threadIdx.x;
    for (int i = tid; i < H; i += 64) e_s[i] = ein[(size_t)c*H + i];
    __syncthreads();
    float acc = 0.f;
#pragma unroll 1
    for (int h = 0; h < H; h += 4){
        float4 ev4 = *reinterpret_cast<const float4*>(&e_s[h]);
        acc = fmaf(ev4.x, we[(h+0)*D + tid], acc);
        acc = fmaf(ev4.y, we[(h+1)*D + tid], acc);
        acc = fmaf(ev4.z, we[(h+2)*D + tid], acc);
        acc = fmaf(ev4.w, we[(h+3)*D + tid], acc);
    }
    acc += be[tid];
    g_ev[c*D + tid]  = acc;
    g_evb[c*D + tid] = __float2bfloat16(acc);
}

// ---------------- K1: dense + RoPE -> qw,kw (fp32) + Qb,Kb (bf16) ----------------
#define K1_M 8
__global__ __launch_bounds__(128) void k1_qk(const float* __restrict__ inp,
                                             const float* __restrict__ wd,
                                             const float* __restrict__ bd){
    __shared__ float in_s[K1_M][H];
    __shared__ float seq_s[K1_M][128];
    const int b = blockIdx.y, m0 = blockIdx.x * K1_M, tid = threadIdx.x;

    const float* src = inp + ((size_t)b*NS + m0) * H;
    for (int i = tid; i < K1_M*H; i += 128) in_s[i/H][i%H] = src[i];
    __syncthreads();

    const int col = tid;
    float acc[K1_M];
#pragma unroll
    for (int mi = 0; mi < K1_M; mi++) acc[mi] = 0.f;
#pragma unroll 1
    for (int h = 0; h < H; h += 4){
        float w0 = wd[(h+0)*128 + col];
        float w1 = wd[(h+1)*128 + col];
        float w2 = wd[(h+2)*128 + col];
        float w3 = wd[(h+3)*128 + col];
#pragma unroll
        for (int mi = 0; mi < K1_M; mi++){
            float4 iv = *reinterpret_cast<const float4*>(&in_s[mi][h]);
            acc[mi] = fmaf(iv.x, w0, acc[mi]);
            acc[mi] = fmaf(iv.y, w1, acc[mi]);
            acc[mi] = fmaf(iv.z, w2, acc[mi]);
            acc[mi] = fmaf(iv.w, w3, acc[mi]);
        }
    }
    const float bb = bd[col];
#pragma unroll
    for (int mi = 0; mi < K1_M; mi++) seq_s[mi][col] = acc[mi] + bb;
    __syncthreads();

    for (int t = tid; t < K1_M*64; t += 128){
        int mi = t >> 6, p = t & 63;
        int which = p >> 5, j = p & 31;
        int m = m0 + mi;
        float divf = (float)exp((double)j * -0.28782313662425574);
        float ang  = (float)m * divf;
        double ad  = (double)ang;
        float cv = (float)cos(ad), sv = (float)sin(ad);
        int base = which*64 + 2*j;
        float x0 = seq_s[mi][base], x1 = seq_s[mi][base+1];
        float r0 = x0*cv - x1*sv;
        float r1 = x1*cv + x0*sv;
        size_t o = ((size_t)b*NS + m) * D + 2*j;
        if (which){
            g_kw[o] = r0; g_kw[o+1] = r1;
            g_Kb[o] = __float2bfloat16(r0); g_Kb[o+1] = __float2bfloat16(r1);
        } else {
            g_qw[o] = r0; g_qw[o+1] = r1;
            g_Qb[o] = __float2bfloat16(r0); g_Qb[o+1] = __float2bfloat16(r1);
        }
    }
}

// ---------------- K_sum2: column sums + chanMax init ----------------
__global__ __launch_bounds__(512) void k_sum2(){
    __shared__ float red[8][64];
    const int which = blockIdx.x, b = blockIdx.y;
    const int tid = threadIdx.x, d = tid & 63, part = tid >> 6;
    if (which == 0 && b == 0 && tid < B*C) g_chanMaxKey[tid] = 0u;
    const float* src = (which ? g_kw : g_qw) + (size_t)b*NS*D;
    float s = 0.f;
#pragma unroll 8
    for (int m = part; m < NS; m += 8) s += src[m*64 + d];
    red[part][d] = s;
    __syncthreads();
    if (tid < 64){
        float t = 0.f;
#pragma unroll
        for (int p = 0; p < 8; p++) t += red[p][tid];
        (which ? g_Ks : g_Qs)[b*64 + tid] = t;
    }
}

// ================= GEMM tile helpers: A = q (128x64), B = ev_c∘k (128x64) =================
__device__ __forceinline__ void load_tiles_qk(char* smem, int b, int c, int m0, int n0, int tid){
    const uint4* pQ = reinterpret_cast<const uint4*>(g_Qb);
    const uint4* pK = reinterpret_cast<const uint4*>(g_Kb);
    const size_t qbase = ((size_t)b*NS + m0) * 8;
    const size_t kbase = ((size_t)b*NS + n0) * 8;
    const int c16 = tid & 7;
    const uint4 ev4 = *reinterpret_cast<const uint4*>(g_evb + c*64 + c16*8);
#pragma unroll
    for (int it = 0; it < 4; it++){
        int i = it*256 + tid;
        int row = i >> 3;
        uint32_t so = swz128(row*128 + c16*16);
        *reinterpret_cast<uint4*>(smem + so) = pQ[qbase + (size_t)row*8 + c16];
        uint4 kv = pK[kbase + (size_t)row*8 + c16];
        kv.x = bmul2(kv.x, ev4.x); kv.y = bmul2(kv.y, ev4.y);
        kv.z = bmul2(kv.z, ev4.z); kv.w = bmul2(kv.w, ev4.w);
        *reinterpret_cast<uint4*>(smem + 16384 + so) = kv;
    }
}
__device__ __forceinline__ void mainloop_128(uint32_t sbA, uint32_t sbB, int warp_m, int warp_n,
                                             int lane, float acc[4][4][4]){
#pragma unroll
    for (int kt = 0; kt < 4; kt++){
        uint32_t af[4][4], bf[4][2];
#pragma unroll
        for (int i = 0; i < 4; i++){
            int row = warp_m*64 + i*16 + (lane & 15);
            ldm_x4(af[i], sbA + swz128(row*128 + kt*32 + (lane >> 4)*16));
        }
#pragma unroll
        for (int j = 0; j < 4; j++){
            int row = warp_n*32 + j*8 + (lane & 7);
            ldm_x2(bf[j], sbB + swz128(row*128 + kt*32 + ((lane >> 3) & 1)*16));
        }
#pragma unroll
        for (int i = 0; i < 4; i++)
#pragma unroll
            for (int j = 0; j < 4; j++)
                mma16816(acc[i][j], af[i], bf[j]);
    }
}

// ---------------- KP1: per-channel max (recompute) ----------------
__global__ __launch_bounds__(256) void kp1_chanmax(){
    __shared__ __align__(1024) char smem[32768];
    __shared__ float red_s[8];
    const uint32_t sbA = smem_u32(smem), sbB = sbA + 16384;
    const int tid = threadIdx.x, wid = tid >> 5, lane = tid & 31;
    const int warp_m = wid >> 2, warp_n = wid & 3;
    const int b = blockIdx.z, rt = blockIdx.y, n0 = blockIdx.x * 128;
    const int c = rt >> 2, m0 = (rt & 3) * 128;

    load_tiles_qk(smem, b, c, m0, n0, tid);
    __syncthreads();

    float acc[4][4][4];
#pragma unroll
    for (int i = 0; i < 4; i++)
#pragma unroll
        for (int j = 0; j < 4; j++)
#pragma unroll
            for (int r = 0; r < 4; r++) acc[i][j][r] = 0.f;
    mainloop_128(sbA, sbB, warp_m, warp_n, lane, acc);

    float mx = -3.402823466e38f;
#pragma unroll
    for (int i = 0; i < 4; i++)
#pragma unroll
        for (int j = 0; j < 4; j++)
#pragma unroll
            for (int r = 0; r < 4; r++) mx = fmaxf(mx, acc[i][j][r]);
#pragma unroll
    for (int off = 16; off > 0; off >>= 1)
        mx = fmaxf(mx, __shfl_xor_sync(0xffffffffu, mx, off));
    if (lane == 0) red_s[wid] = mx;
    __syncthreads();
    if (tid == 0){
        float m2 = red_s[0];
#pragma unroll
        for (int w = 1; w < 8; w++) m2 = fmaxf(m2, red_s[w]);
        atomicMax(&g_chanMaxKey[b*C + c], fkey(m2));
    }
}

// ---------------- K3: scale + evS ----------------
__global__ __launch_bounds__(128) void k3_scale(const float* __restrict__ w1, const float* __restrict__ b1,
                                                const float* __restrict__ w2, const float* __restrict__ b2){
    __shared__ float avg_s[C], mx_s[C], hid_s[12], sc_s[C];
    const int tid = threadIdx.x;
    for (int b = 0; b < B; b++){
        if (tid < C){
            float s = 0.f;
            for (int d = 0; d < D; d++)
                s = fmaf(g_ev[tid*D + d], g_Qs[b*D + d]*g_Ks[b*D + d], s);
            avg_s[tid] = s * (1.f/262144.f);
            mx_s[tid]  = fkeyinv(g_chanMaxKey[b*C + tid]);
        }
        __syncthreads();
        if (tid < 12){
            int which = tid / 6, j = tid % 6;
            const float* v = which ? mx_s : avg_s;
            float h = b1[j];
            for (int c2 = 0; c2 < C; c2++) h = fmaf(v[c2], w1[c2*CH_HID + j], h);
            hid_s[tid] = fmaxf(h, 0.f);
        }
        __syncthreads();
        if (tid < C){
            float z = 2.f * b2[tid];
            for (int j = 0; j < CH_HID; j++)
                z = fmaf(hid_s[j] + hid_s[6+j], w2[j*C + tid], z);
            float sc = 1.f / (1.f + expf(-z));
            g_scale[b*C + tid] = sc;
            sc_s[tid] = sc;
        }
        __syncthreads();
        if (tid < D){
            float s = 0.f;
            for (int c2 = 0; c2 < C; c2++)
                s = fmaf(sc_s[c2], g_ev[c2*D + tid], s);
            g_evSb[b*D + tid] = __float2bfloat16(s);
        }
        __syncthreads();
    }
}

// ---------------- KP2: register-resident channel loop, 4-way channel split ----------------
// tile m=64 x n=64; 256 thr (8 warps: 4m x 2n, warp tile 16x32). Frags loaded once;
// per channel: scale B frags by ev pairs (bf16x2), mma, update max. Split 3 adds the
// evS pseudo-channel for the exact mean. 1024 blocks -> ~7/SM.
__global__ __launch_bounds__(256) void kp2_comp(){
    __shared__ __align__(1024) char smQ[8192];
    __shared__ __align__(1024) char smK[8192];
    __shared__ __nv_bfloat16 s_evb[CSPL*D];    // 3.4 KB slice
    __shared__ __nv_bfloat16 s_evS[D];
    __shared__ float sc_s[CSPL];
    const uint32_t sQ = smem_u32(smQ), sK = smem_u32(smK);
    const uint32_t sEV = smem_u32(s_evb);
    const int tid = threadIdx.x, wid = tid >> 5, lane = tid & 31;
    const int warp_m = wid >> 1, warp_n = wid & 1;
    const int z = blockIdx.z;
    const int b = z >> 2, split = z & 3;
    const int c0 = split * CSPL;
    const int m0 = blockIdx.y * 64, n0 = blockIdx.x * 64;

    if (tid < CSPL) sc_s[tid] = g_scale[b*C + c0 + tid];
    if (tid < D) s_evS[tid] = g_evSb[b*D + tid];
    for (int i = tid; i < CSPL*D/8; i += 256)
        reinterpret_cast<uint4*>(s_evb)[i] = reinterpret_cast<const uint4*>(g_evb + c0*D)[i];
    {
        const uint4* pQ = reinterpret_cast<const uint4*>(g_Qb);
        const uint4* pK = reinterpret_cast<const uint4*>(g_Kb);
        const size_t qbase = ((size_t)b*NS + m0) * 8;
        const size_t kbase = ((size_t)b*NS + n0) * 8;
#pragma unroll
        for (int it = 0; it < 2; it++){
            int i = it*256 + tid;
            int row = i >> 3, c16 = i & 7;
            uint32_t so = swz128(row*128 + c16*16);
            *reinterpret_cast<uint4*>(smQ + so) = pQ[qbase + (size_t)row*8 + c16];
            *reinterpret_cast<uint4*>(smK + so) = pK[kbase + (size_t)row*8 + c16];
        }
    }
    __syncthreads();

    uint32_t af[4][4];
#pragma unroll
    for (int kt = 0; kt < 4; kt++){
        int row = warp_m*16 + (lane & 15);
        ldm_x4(af[kt], sQ + swz128(row*128 + kt*32 + (lane >> 4)*16));
    }
    uint32_t bf[4][4][2];
#pragma unroll
    for (int kt = 0; kt < 4; kt++)
#pragma unroll
        for (int j = 0; j < 4; j++){
            int row = warp_n*32 + j*8 + (lane & 7);
            ldm_x2(bf[kt][j], sK + swz128(row*128 + kt*32 + ((lane >> 3) & 1)*16));
        }

    const int dlo = (lane & 3)*2;

    float mx[4][4];
#pragma unroll
    for (int j = 0; j < 4; j++)
#pragma unroll
        for (int r = 0; r < 4; r++) mx[j][r] = -3.402823466e38f;

#pragma unroll 1
    for (int c = 0; c < CSPL; c++){
        uint32_t ev[4][2];
#pragma unroll
        for (int kt = 0; kt < 4; kt++)
#pragma unroll
            for (int reg = 0; reg < 2; reg++){
                uint32_t addr = sEV + (c*64 + kt*16 + reg*8 + dlo)*2;
                asm volatile("ld.shared.b32 %0, [%1];" : "=r"(ev[kt][reg]) : "r"(addr));
            }
        float acc[4][4];
#pragma unroll
        for (int j = 0; j < 4; j++)
#pragma unroll
            for (int r = 0; r < 4; r++) acc[j][r] = 0.f;
#pragma unroll
        for (int kt = 0; kt < 4; kt++)
#pragma unroll
            for (int j = 0; j < 4; j++){
                uint32_t sb[2];
                sb[0] = bmul2(bf[kt][j][0], ev[kt][0]);
                sb[1] = bmul2(bf[kt][j][1], ev[kt][1]);
                mma16816(acc[j], af[kt], sb);
            }
        const float sc = sc_s[c];
#pragma unroll
        for (int j = 0; j < 4; j++)
#pragma unroll
            for (int r = 0; r < 4; r++)
                mx[j][r] = fmaxf(mx[j][r], acc[j][r] * sc);
    }

    float* outb = g_cmax[split];
#pragma unroll
    for (int j = 0; j < 4; j++){
        int gm0 = m0 + warp_m*16 + (lane >> 2);
        int gn  = n0 + warp_n*32 + j*8 + (lane & 3)*2;
        size_t p0 = ((size_t)(b*NS + gm0))*NS + gn;
        size_t p1 = ((size_t)(b*NS + gm0 + 8))*NS + gn;
        *reinterpret_cast<float2*>(&outb[p0]) = make_float2(mx[j][0], mx[j][1]);
        *reinterpret_cast<float2*>(&outb[p1]) = make_float2(mx[j][2], mx[j][3]);
    }

    if (split == 3){
        // mean via evS pseudo-channel (exact factorization)
        uint32_t ev[4][2];
        const uint32_t sES = smem_u32(s_evS);
#pragma unroll
        for (int kt = 0; kt < 4; kt++)
#pragma unroll
            for (int reg = 0; reg < 2; reg++){
                uint32_t addr = sES + (kt*16 + reg*8 + dlo)*2;
                asm volatile("ld.shared.b32 %0, [%1];" : "=r"(ev[kt][reg]) : "r"(addr));
            }
        float acc[4][4];
#pragma unroll
        for (int j = 0; j < 4; j++)
#pragma unroll
            for (int r = 0; r < 4; r++) acc[j][r] = 0.f;
#pragma unroll
        for (int kt = 0; kt < 4; kt++)
#pragma unroll
            for (int j = 0; j < 4; j++){
                uint32_t sb[2];
                sb[0] = bmul2(bf[kt][j][0], ev[kt][0]);
                sb[1] = bmul2(bf[kt][j][1], ev[kt][1]);
                mma16816(acc[j], af[kt], sb);
            }
#pragma unroll
        for (int j = 0; j < 4; j++){
            int gm0 = m0 + warp_m*16 + (lane >> 2);
            int gn  = n0 + warp_n*32 + j*8 + (lane & 3)*2;
            size_t p0 = ((size_t)(b*NS + gm0))*NS + gn;
            size_t p1 = ((size_t)(b*NS + gm0 + 8))*NS + gn;
            *reinterpret_cast<float2*>(&g_compMean[p0]) = make_float2(acc[j][0]*(1.f/108.f), acc[j][1]*(1.f/108.f));
            *reinterpret_cast<float2*>(&g_compMean[p1]) = make_float2(acc[j][2]*(1.f/108.f), acc[j][3]*(1.f/108.f));
        }
    }
}

// ---------------- K5: 7x7 conv + sigmoid (combines 4 max splits) ----------------
#define CT 16
__global__ __launch_bounds__(256) void k5_conv(const float* __restrict__ cw){
    __shared__ float smax[CT+6][CT+6];
    __shared__ float smean[CT+6][CT+6];
    __shared__ float w_s[98];
    const int b = blockIdx.z, m0 = blockIdx.y*CT, n0 = blockIdx.x*CT, tid = threadIdx.x;
    if (tid < 98) w_s[tid] = cw[tid];
    for (int i = tid; i < (CT+6)*(CT+6); i += 256){
        int r = i / (CT+6), cc = i % (CT+6);
        int gm = m0 + r - 3, gn = n0 + cc - 3;
        float a = 0.f, mn = 0.f;
        if (gm >= 0 && gm < NS && gn >= 0 && gn < NS){
            size_t gi = (size_t)(b*NS + gm)*NS + gn;
            a = fmaxf(fmaxf(g_cmax[0][gi], g_cmax[1][gi]),
                      fmaxf(g_cmax[2][gi], g_cmax[3][gi]));
            mn = g_compMean[gi];
        }
        smax[r][cc] = a; smean[r][cc] = mn;
    }
    __syncthreads();
    const int ty = tid / CT, tx = tid % CT;
    float acc = 0.f;
#pragma unroll
    for (int kh = 0; kh < 7; kh++)
#pragma unroll
        for (int kw = 0; kw < 7; kw++){
            acc = fmaf(smax[ty+kh][tx+kw],  w_s[kh*7 + kw],      acc);
            acc = fmaf(smean[ty+kh][tx+kw], w_s[49 + kh*7 + kw], acc);
        }
    acc *= 0.9999950000374997f;
    g_sig[(size_t)(b*NS + m0 + ty)*NS + n0 + tx] = 1.f / (1.f + expf(-acc));
}

// ---------------- KP3: recompute -> fused final epilogue -> out ----------------
__global__ __launch_bounds__(256) void kp3_final(float* __restrict__ out, const int* __restrict__ mask){
    __shared__ __align__(1024) char smem[32768];
    __shared__ int mrow_s[128], mcol_s[128];
    const uint32_t sbA = smem_u32(smem), sbB = sbA + 16384;
    const int tid = threadIdx.x, wid = tid >> 5, lane = tid & 31;
    const int warp_m = wid >> 2, warp_n = wid & 3;
    const int b = blockIdx.z, rt = blockIdx.y, n0 = blockIdx.x * 128;
    const int c = rt >> 2, m0 = (rt & 3) * 128;

    load_tiles_qk(smem, b, c, m0, n0, tid);
    if (tid < 128){
        mrow_s[tid] = mask[b*NS + m0 + tid];
        mcol_s[tid] = mask[b*NS + n0 + tid];
    }
    __syncthreads();

    float acc[4][4][4];
#pragma unroll
    for (int i = 0; i < 4; i++)
#pragma unroll
        for (int j = 0; j < 4; j++)
#pragma unroll
            for (int r = 0; r < 4; r++) acc[i][j][r] = 0.f;
    mainloop_128(sbA, sbB, warp_m, warp_n, lane, acc);

    const float sc = g_scale[b*C + c];
    const size_t obase = ((size_t)(b*C + c)*NS + m0)*NS + n0;
    const float NEGINF = __int_as_float(0xff800000);
#pragma unroll
    for (int i = 0; i < 4; i++){
        int lrow0 = warp_m*64 + i*16 + (lane >> 2);
#pragma unroll
        for (int j = 0; j < 4; j++){
            int lcol = warp_n*32 + j*8 + (lane & 3)*2;
            int gn = n0 + lcol;
            int mc0 = mcol_s[lcol], mc1 = mcol_s[lcol+1];
#pragma unroll
            for (int h = 0; h < 2; h++){
                int lrow = lrow0 + h*8;
                int gm = m0 + lrow;
                float2 sg = *reinterpret_cast<const float2*>(&g_sig[((size_t)(b*NS + gm))*NS + gn]);
                int mr = mrow_s[lrow];
                float y0 = acc[i][j][2*h]   * fmaf(sc, sg.x, 1.f);
                float y1 = acc[i][j][2*h+1] * fmaf(sc, sg.y, 1.f);
                if (gm > gn)     y0 -= 1e12f;
                if (gm > gn + 1) y1 -= 1e12f;
                if (mr == 0 || mc0 == 0) y0 = NEGINF;
                if (mr == 0 || mc1 == 0) y1 = NEGINF;
                *reinterpret_cast<float2*>(&out[obase + (size_t)lrow*NS + lcol]) =
                    make_float2(y0 * 0.125f, y1 * 0.125f);
            }
        }
    }
}

// ---------------- launcher ----------------
extern "C" void kernel_launch(void* const* d_in, const int* in_sizes, int n_in,
                              void* d_out, int out_size){
    (void)in_sizes; (void)n_in; (void)out_size;
    const float* inputs       = (const float*)d_in[0];
    const float* event_inputs = (const float*)d_in[1];
    const int*   mask         = (const int*)  d_in[2];
    const float* w_dense      = (const float*)d_in[3];
    const float* b_dense      = (const float*)d_in[4];
    const float* w_event      = (const float*)d_in[5];
    const float* b_event      = (const float*)d_in[6];
    const float* mlp_w1       = (const float*)d_in[7];
    const float* mlp_b1       = (const float*)d_in[8];
    const float* mlp_w2       = (const float*)d_in[9];
    const float* mlp_b2       = (const float*)d_in[10];
    const float* conv_w       = (const float*)d_in[11];
    float* out = (float*)d_out;

    k1b_ev<<<108, 64>>>(event_inputs, w_event, b_event);
    k1_qk<<<dim3(64, 2), 128>>>(inputs, w_dense, b_dense);
    k_sum2<<<dim3(2, 2), 512>>>();
    kp1_chanmax<<<dim3(4, 432, 2), 256>>>();
    k3_scale<<<1, 128>>>(mlp_w1, mlp_b1, mlp_w2, mlp_b2);
    kp2_comp<<<dim3(8, 8, 2*NSPLIT), 256>>>();
    k5_conv<<<dim3(32, 32, 2), 256>>>(conv_w);
    kp3_final<<<dim3(4, 432, 2), 256>>>(out, mask);
}